// round 7
// baseline (speedup 1.0000x reference)
#include <cuda_runtime.h>
#include <cuda_fp16.h>
#include <math.h>
#include <stdint.h>

#define NN 20000
#define ETOT 150000
#define LPART 75000
#define FINC 256
#define HC 512
#define H2C 1024

// ---------------- static device scratch ----------------
__device__ float g_sfdf[NN * 2048];     // layer0 merged projections
__device__ float g_y[NN * HC];
__device__ float g_x1[NN * HC];
__device__ __half g_xh[NN * FINC];
__device__ __half g_ob[NN * HC];
__device__ __half g_hb[NN * H2C];
__device__ __half g_wcat[2048 * FINC];  // [l*1024 + (src?0:512) + row][k]
__device__ __half g_w01[2 * H2C * HC], g_w02[2 * HC * H2C];
__device__ __half g_w11[2 * H2C * HC], g_w12[2 * HC * H2C];
__device__ int g_rowptr[2][NN + 1];
__device__ int g_cursor[2][NN];
__device__ int g_eidx[2][LPART];

// ---------------- small utility kernels ----------------
__global__ void k_zero_int(int* p, int n) {
    int i = blockIdx.x * blockDim.x + threadIdx.x;
    if (i < n) p[i] = 0;
}

__global__ void k_count_deg(const int* __restrict__ dst, int L, int* __restrict__ deg) {
    int i = blockIdx.x * blockDim.x + threadIdx.x;
    if (i < L) atomicAdd(&deg[dst[i]], 1);
}

__global__ void k_scan(const int* __restrict__ deg, int* __restrict__ rowptr, int n) {
    __shared__ int sbuf[1024];
    __shared__ int carry;
    int t = threadIdx.x;
    if (t == 0) { carry = 0; rowptr[0] = 0; }
    __syncthreads();
    for (int base = 0; base < n; base += 1024) {
        int v = (base + t < n) ? deg[base + t] : 0;
        sbuf[t] = v;
        __syncthreads();
        for (int off = 1; off < 1024; off <<= 1) {
            int nv = (t >= off) ? sbuf[t - off] : 0;
            __syncthreads();
            sbuf[t] += nv;
            __syncthreads();
        }
        if (base + t < n) rowptr[base + t + 1] = carry + sbuf[t];
        __syncthreads();
        if (t == 0) carry += sbuf[1023];
        __syncthreads();
    }
}

__global__ void k_copy_int(const int* __restrict__ a, int* __restrict__ b, int n) {
    int i = blockIdx.x * blockDim.x + threadIdx.x;
    if (i < n) b[i] = a[i];
}

__global__ void k_scatter(const int* __restrict__ dst, int L, int* __restrict__ cursor,
                          int* __restrict__ eidx) {
    int i = blockIdx.x * blockDim.x + threadIdx.x;
    if (i < L) {
        int pos = atomicAdd(&cursor[dst[i]], 1);
        eidx[pos] = i;
    }
}

__global__ void k_sort_buckets(const int* __restrict__ rowptr, int* __restrict__ eidx) {
    int node = blockIdx.x * blockDim.x + threadIdx.x;
    if (node >= NN) return;
    int a = rowptr[node], b = rowptr[node + 1];
    for (int i = a + 1; i < b; i++) {
        int key = eidx[i];
        int j = i - 1;
        while (j >= a && eidx[j] > key) { eidx[j + 1] = eidx[j]; j--; }
        eidx[j + 1] = key;
    }
}

__global__ void k_leaky(const float* __restrict__ y, float* __restrict__ x1, int n) {
    int i = blockIdx.x * blockDim.x + threadIdx.x;
    if (i < n) {
        float v = y[i];
        x1[i] = v > 0.f ? v : 0.01f * v;
    }
}

__global__ void k_half(const float* __restrict__ s, __half* __restrict__ h, int n) {
    int i = blockIdx.x * blockDim.x + threadIdx.x;
    if (i < n) h[i] = __float2half(s[i]);
}

// scatter l0_src/l0_dst into the concatenated projection weight
// src layout: [2][512][256]; dst rows: l*1024 + off + row
__global__ void k_half_cat(const float* __restrict__ s, __half* __restrict__ wcat, int off) {
    int i = blockIdx.x * blockDim.x + threadIdx.x;
    if (i >= 2 * HC * FINC) return;
    int l = i >> 17;             // 512*256 = 131072
    int rem = i & 131071;
    int rr = rem >> 8;
    int c = rem & 255;
    wcat[((l * 1024 + off + rr) << 8) + c] = __float2half(s[i]);
}

// ---------------- fused per-node edge softmax aggregation (fp16 out) -------------
__global__ __launch_bounds__(128) void k_agg(
    const float* __restrict__ sfeat, const float* __restrict__ dfeat,
    int sstr, int dstr,
    const float* __restrict__ We, const float* __restrict__ ea,
    const int* __restrict__ srcIdx, const int* __restrict__ rowptr,
    const int* __restrict__ eidx, __half* __restrict__ oh)
{
    __shared__ float wsh[HC];
    int t = threadIdx.x;
    for (int i = t; i < HC; i += 128) wsh[i] = We[i];
    __syncthreads();
    int warp = t >> 5, lane = t & 31;
    int node = blockIdx.x * 4 + warp;
    if (node >= NN) return;

    float wv[16];
#pragma unroll
    for (int j = 0; j < 16; j++) wv[j] = wsh[lane + 32 * j];

    float m[16], s[16], tt[16];
#pragma unroll
    for (int j = 0; j < 16; j++) { m[j] = -INFINITY; s[j] = 0.f; tt[j] = 0.f; }

    int e0 = rowptr[node], e1 = rowptr[node + 1];
    for (int e = e0; e < e1; e++) {
        int eid = eidx[e];
        int sidx = srcIdx[eid];
        float a = ea[eid];
        const float* row = sfeat + (size_t)sidx * sstr;
#pragma unroll
        for (int j = 0; j < 16; j++) {
            float msg = fmaxf(row[lane + 32 * j] + a * wv[j], 0.f) + 1e-7f;
            float mn = fmaxf(m[j], msg);
            float scale = __expf(m[j] - mn);
            float p = __expf(msg - mn);
            s[j] = s[j] * scale + p;
            tt[j] = tt[j] * scale + msg * p;
            m[j] = mn;
        }
    }
    const float* drow = dfeat + (size_t)node * dstr;
    __half* hrow = oh + (size_t)node * HC;
#pragma unroll
    for (int j = 0; j < 16; j++) {
        float v = tt[j] / (s[j] + 1e-16f) + drow[lane + 32 * j];
        hrow[lane + 32 * j] = __float2half(v);
    }
}

// ---------------- fp16 tensor-core GEMM (NT), cp.async 4-stage, 128x256 block ----
// 256 threads, 8 warps of 64x64 (4x8 m16n8k16 atoms).
// mode 0: fp32 out (+accum). mode 1: BN+ReLU -> fp16 out.
#define BM 128
#define BN 256
#define BK 32
#define BKH 40
#define STG 4
#define TILE_A_B (BM * BKH * 2)            // 10240
#define TILE_B_B (BN * BKH * 2)            // 20480
#define STAGE_B (TILE_A_B + TILE_B_B)      // 30720
#define DSMEM (STG * STAGE_B)              // 122880

__device__ __forceinline__ void mma_f16(float* c, const uint32_t* a, uint32_t b0, uint32_t b1) {
    asm volatile(
        "mma.sync.aligned.m16n8k16.row.col.f32.f16.f16.f32 "
        "{%0,%1,%2,%3}, {%4,%5,%6,%7}, {%8,%9}, {%0,%1,%2,%3};"
        : "+f"(c[0]), "+f"(c[1]), "+f"(c[2]), "+f"(c[3])
        : "r"(a[0]), "r"(a[1]), "r"(a[2]), "r"(a[3]), "r"(b0), "r"(b1));
}

__device__ __forceinline__ void cp16(uint32_t saddr, const void* gaddr, int srcbytes) {
    asm volatile("cp.async.cg.shared.global [%0], [%1], 16, %2;"
                 :: "r"(saddr), "l"(gaddr), "r"(srcbytes));
}

__global__ __launch_bounds__(256) void k_hgemm(
    const __half* __restrict__ A, const __half* __restrict__ B,
    int M, int K, int Ncols, int mode,
    const float* __restrict__ gv, const float* __restrict__ bv,
    const float* __restrict__ mv, const float* __restrict__ vv,
    float* __restrict__ Cf, __half* __restrict__ Ch, int accum)
{
    extern __shared__ __align__(128) char smc[];
    uint32_t sbase = (uint32_t)__cvta_generic_to_shared(smc);

    int tid = threadIdx.x;
    int tileM = blockIdx.y * BM, tileN = blockIdx.x * BN;
    int warp = tid >> 5, lane = tid & 31;
    int g8 = lane >> 2, t4 = lane & 3;
    int wm = (warp & 1) * 64;
    int wn = (warp >> 1) * 64;

    const __half* Ag = A + (size_t)tileM * K;
    const __half* Bg = B + (size_t)tileN * K;

    // A: 2 chunks/thread (512 total), B: 4 chunks/thread (1024 total)
    int ra0 = tid >> 2, ca0 = (tid & 3) * 8;
    int ra1 = (tid + 256) >> 2, ca1 = ((tid + 256) & 3) * 8;
    int szA0 = (tileM + ra0) < M ? 16 : 0;
    int szA1 = (tileM + ra1) < M ? 16 : 0;
    uint32_t dA0 = sbase + (uint32_t)(ra0 * (BKH * 2) + ca0 * 2);
    uint32_t dA1 = sbase + (uint32_t)(ra1 * (BKH * 2) + ca1 * 2);
    int rb[4], cbs[4];
    uint32_t dB[4];
#pragma unroll
    for (int q = 0; q < 4; q++) {
        int qq = tid + q * 256;
        rb[q] = qq >> 2;
        cbs[q] = (qq & 3) * 8;
        dB[q] = sbase + TILE_A_B + (uint32_t)(rb[q] * (BKH * 2) + cbs[q] * 2);
    }

    float acc[4][8][4];
#pragma unroll
    for (int i = 0; i < 4; i++)
#pragma unroll
        for (int j = 0; j < 8; j++)
#pragma unroll
            for (int r = 0; r < 4; r++) acc[i][j][r] = 0.f;

    int nt = K / BK;

#define HISSUE(tile, stage)                                                     \
    do {                                                                        \
        int kb_ = (tile) * BK;                                                  \
        uint32_t so_ = (uint32_t)((stage) * STAGE_B);                           \
        cp16(dA0 + so_, Ag + (size_t)ra0 * K + kb_ + ca0, szA0);                \
        cp16(dA1 + so_, Ag + (size_t)ra1 * K + kb_ + ca1, szA1);                \
        cp16(dB[0] + so_, Bg + (size_t)rb[0] * K + kb_ + cbs[0], 16);           \
        cp16(dB[1] + so_, Bg + (size_t)rb[1] * K + kb_ + cbs[1], 16);           \
        cp16(dB[2] + so_, Bg + (size_t)rb[2] * K + kb_ + cbs[2], 16);           \
        cp16(dB[3] + so_, Bg + (size_t)rb[3] * K + kb_ + cbs[3], 16);           \
    } while (0)

#pragma unroll
    for (int s = 0; s < STG - 1; s++) {
        if (s < nt) HISSUE(s, s);
        asm volatile("cp.async.commit_group;");
    }

    for (int t = 0; t < nt; t++) {
        asm volatile("cp.async.wait_group %0;" :: "n"(STG - 2));
        __syncthreads();

        int ntile = t + STG - 1;
        if (ntile < nt) HISSUE(ntile, ntile & (STG - 1));
        asm volatile("cp.async.commit_group;");

        const __half* as = (const __half*)(smc + (t & (STG - 1)) * STAGE_B);
        const __half* bs = (const __half*)(smc + (t & (STG - 1)) * STAGE_B + TILE_A_B);

#pragma unroll
        for (int kk = 0; kk < 2; kk++) {
            int kb = kk * 16 + 2 * t4;
            uint32_t af[4][4];
#pragma unroll
            for (int i = 0; i < 4; i++) {
                int rr = wm + i * 16 + g8;
                af[i][0] = *(const uint32_t*)(as + rr * BKH + kb);
                af[i][1] = *(const uint32_t*)(as + (rr + 8) * BKH + kb);
                af[i][2] = *(const uint32_t*)(as + rr * BKH + kb + 8);
                af[i][3] = *(const uint32_t*)(as + (rr + 8) * BKH + kb + 8);
            }
#pragma unroll
            for (int j = 0; j < 8; j++) {
                int n0 = wn + j * 8 + g8;
                uint32_t bf0 = *(const uint32_t*)(bs + n0 * BKH + kb);
                uint32_t bf1 = *(const uint32_t*)(bs + n0 * BKH + kb + 8);
#pragma unroll
                for (int i = 0; i < 4; i++) mma_f16(acc[i][j], af[i], bf0, bf1);
            }
        }
    }

    // ---- epilogue ----
#pragma unroll
    for (int i = 0; i < 4; i++) {
#pragma unroll
        for (int h8 = 0; h8 < 2; h8++) {
            int r = tileM + wm + i * 16 + g8 + h8 * 8;
            if (r >= M) continue;
#pragma unroll
            for (int j = 0; j < 8; j++) {
                int c = tileN + wn + j * 8 + t4 * 2;
                float v0 = acc[i][j][h8 * 2 + 0];
                float v1 = acc[i][j][h8 * 2 + 1];
                if (mode == 1) {
                    float s0 = gv[c] * rsqrtf(vv[c] + 1e-5f);
                    float s1 = gv[c + 1] * rsqrtf(vv[c + 1] + 1e-5f);
                    v0 = fmaxf((v0 - mv[c]) * s0 + bv[c], 0.f);
                    v1 = fmaxf((v1 - mv[c + 1]) * s1 + bv[c + 1], 0.f);
                    __half2 hv;
                    hv.x = __float2half(v0);
                    hv.y = __float2half(v1);
                    *(__half2*)(Ch + (size_t)r * Ncols + c) = hv;
                } else {
                    float* crow = Cf + (size_t)r * Ncols + c;
                    if (accum) {
                        float2 old = *(const float2*)crow;
                        v0 += old.x;
                        v1 += old.y;
                    }
                    *(float2*)crow = make_float2(v0, v1);
                }
            }
        }
    }
}

// ---------------- host orchestration ----------------
extern "C" void kernel_launch(void* const* d_in, const int* in_sizes, int n_in,
                              void* d_out, int out_size) {
    const float* x  = (const float*)d_in[0];
    const int*   ei = (const int*)d_in[1];
    const float* ea = (const float*)d_in[2];
    int base = 3;
    if (n_in > 19) base = 3 + (n_in - 19);
    const float* l0_src  = (const float*)d_in[base + 0];
    const float* l0_dst  = (const float*)d_in[base + 1];
    const float* l0_edge = (const float*)d_in[base + 2];
    const float* l0_w1   = (const float*)d_in[base + 3];
    const float* l0_g    = (const float*)d_in[base + 4];
    const float* l0_b    = (const float*)d_in[base + 5];
    const float* l0_m    = (const float*)d_in[base + 6];
    const float* l0_v    = (const float*)d_in[base + 7];
    const float* l0_w2   = (const float*)d_in[base + 8];
    const float* l1_edge = (const float*)d_in[base + 9];
    const float* l1_w1   = (const float*)d_in[base + 10];
    const float* l1_g    = (const float*)d_in[base + 11];
    const float* l1_b    = (const float*)d_in[base + 12];
    const float* l1_m    = (const float*)d_in[base + 13];
    const float* l1_v    = (const float*)d_in[base + 14];
    const float* l1_w2   = (const float*)d_in[base + 15];
    float* out = (float*)d_out;

    float *sfdf, *yb, *x1b;
    __half *xh, *ob, *hb, *wcat, *w01, *w02, *w11, *w12;
    int *rowptr, *cursor, *eidx;
    cudaGetSymbolAddress((void**)&sfdf, g_sfdf);
    cudaGetSymbolAddress((void**)&yb, g_y);
    cudaGetSymbolAddress((void**)&x1b, g_x1);
    cudaGetSymbolAddress((void**)&xh, g_xh);
    cudaGetSymbolAddress((void**)&ob, g_ob);
    cudaGetSymbolAddress((void**)&hb, g_hb);
    cudaGetSymbolAddress((void**)&wcat, g_wcat);
    cudaGetSymbolAddress((void**)&w01, g_w01);
    cudaGetSymbolAddress((void**)&w02, g_w02);
    cudaGetSymbolAddress((void**)&w11, g_w11);
    cudaGetSymbolAddress((void**)&w12, g_w12);
    cudaGetSymbolAddress((void**)&rowptr, g_rowptr);
    cudaGetSymbolAddress((void**)&cursor, g_cursor);
    cudaGetSymbolAddress((void**)&eidx, g_eidx);

    cudaFuncSetAttribute(k_hgemm, cudaFuncAttributeMaxDynamicSharedMemorySize, DSMEM);

    const int offs[2] = {0, LPART};

    // ---- fp16 operand conversion ----
    k_half<<<(NN * FINC + 255) / 256, 256>>>(x, xh, NN * FINC);
    k_half_cat<<<(2 * HC * FINC + 255) / 256, 256>>>(l0_src, wcat, 0);
    k_half_cat<<<(2 * HC * FINC + 255) / 256, 256>>>(l0_dst, wcat, 512);
    k_half<<<(2 * H2C * HC + 255) / 256, 256>>>(l0_w1, w01, 2 * H2C * HC);
    k_half<<<(2 * HC * H2C + 255) / 256, 256>>>(l0_w2, w02, 2 * HC * H2C);
    k_half<<<(2 * H2C * HC + 255) / 256, 256>>>(l1_w1, w11, 2 * H2C * HC);
    k_half<<<(2 * HC * H2C + 255) / 256, 256>>>(l1_w2, w12, 2 * HC * H2C);

    // ---- CSR build ----
    for (int p = 0; p < 2; p++) {
        int* rp = rowptr + p * (NN + 1);
        int* cu = cursor + p * NN;
        int* ex = eidx + p * LPART;
        const int* dstp = ei + ETOT + offs[p];
        k_zero_int<<<(NN + 255) / 256, 256>>>(cu, NN);
        k_count_deg<<<(LPART + 255) / 256, 256>>>(dstp, LPART, cu);
        k_scan<<<1, 1024>>>(cu, rp, NN);
        k_copy_int<<<(NN + 255) / 256, 256>>>(rp, cu, NN);
        k_scatter<<<(LPART + 255) / 256, 256>>>(dstp, LPART, cu, ex);
        k_sort_buckets<<<(NN + 127) / 128, 128>>>(rp, ex);
    }

    dim3 blk(256);
    int gy = (NN + BM - 1) / BM;  // 157
    dim3 gproj(2048 / BN, gy), g512(HC / BN, gy), g1024(H2C / BN, gy);

    // ---- layer 0: merged projection GEMM ----
    k_hgemm<<<gproj, blk, DSMEM>>>(xh, wcat, NN, FINC, 2048, 0,
                                   nullptr, nullptr, nullptr, nullptr,
                                   sfdf, nullptr, 0);

    for (int l = 0; l < 2; l++) {
        k_agg<<<(NN + 3) / 4, 128>>>(sfdf + l * 1024, sfdf + l * 1024 + 512, 2048, 2048,
                                     l0_edge + (size_t)l * HC, ea + offs[l],
                                     ei + offs[l], rowptr + l * (NN + 1),
                                     eidx + l * LPART, ob);
        k_hgemm<<<g1024, blk, DSMEM>>>(ob, w01 + (size_t)l * H2C * HC,
                                       NN, HC, H2C, 1,
                                       l0_g + l * H2C, l0_b + l * H2C,
                                       l0_m + l * H2C, l0_v + l * H2C,
                                       nullptr, hb, 0);
        k_hgemm<<<g512, blk, DSMEM>>>(hb, w02 + (size_t)l * HC * H2C,
                                      NN, H2C, HC, 0, nullptr, nullptr, nullptr, nullptr,
                                      yb, nullptr, l > 0);
    }

    k_leaky<<<(NN * HC + 255) / 256, 256>>>(yb, x1b, NN * HC);

    // ---- layer 1 (sf = df = x1, stride 512) ----
    for (int l = 0; l < 2; l++) {
        k_agg<<<(NN + 3) / 4, 128>>>(x1b, x1b, HC, HC,
                                     l1_edge + (size_t)l * HC, ea + offs[l],
                                     ei + offs[l], rowptr + l * (NN + 1),
                                     eidx + l * LPART, ob);
        k_hgemm<<<g1024, blk, DSMEM>>>(ob, w11 + (size_t)l * H2C * HC,
                                       NN, HC, H2C, 1,
                                       l1_g + l * H2C, l1_b + l * H2C,
                                       l1_m + l * H2C, l1_v + l * H2C,
                                       nullptr, hb, 0);
        k_hgemm<<<g512, blk, DSMEM>>>(hb, w12 + (size_t)l * HC * H2C,
                                      NN, H2C, HC, 0, nullptr, nullptr, nullptr, nullptr,
                                      out, nullptr, l > 0);
    }
}

// round 9
// speedup vs baseline: 1.3854x; 1.3854x over previous
#include <cuda_runtime.h>
#include <cuda_fp16.h>
#include <math.h>
#include <stdint.h>

#define NN 20000
#define ETOT 150000
#define LPART 75000
#define FINC 256
#define HC 512
#define H2C 1024

// ---------------- static device scratch ----------------
__device__ float g_sfdf[NN * 2048];
__device__ float g_y[NN * HC];        // y, then x1 (leaky fused in-place)
__device__ __half g_xh[NN * FINC];
__device__ __half g_ob[NN * HC];
__device__ __half g_hb[NN * H2C];
__device__ __half g_wcat[2048 * FINC];
__device__ __half g_w01[2 * H2C * HC], g_w02[2 * HC * H2C];
__device__ __half g_w11[2 * H2C * HC], g_w12[2 * HC * H2C];
__device__ int g_rowptr[2][NN + 1];
__device__ int g_cursor[2][NN];
__device__ int g_eidx[2][LPART];

// ---------------- small utility kernels ----------------
__global__ void k_zero_int(int* p, int n) {
    int i = blockIdx.x * blockDim.x + threadIdx.x;
    if (i < n) p[i] = 0;
}

__global__ void k_count_deg(const int* __restrict__ dst, int L, int* __restrict__ deg) {
    int i = blockIdx.x * blockDim.x + threadIdx.x;
    if (i < L) atomicAdd(&deg[dst[i]], 1);
}

__global__ void k_scan(const int* __restrict__ deg, int* __restrict__ rowptr, int n) {
    __shared__ int sbuf[1024];
    __shared__ int carry;
    int t = threadIdx.x;
    if (t == 0) { carry = 0; rowptr[0] = 0; }
    __syncthreads();
    for (int base = 0; base < n; base += 1024) {
        int v = (base + t < n) ? deg[base + t] : 0;
        sbuf[t] = v;
        __syncthreads();
        for (int off = 1; off < 1024; off <<= 1) {
            int nv = (t >= off) ? sbuf[t - off] : 0;
            __syncthreads();
            sbuf[t] += nv;
            __syncthreads();
        }
        if (base + t < n) rowptr[base + t + 1] = carry + sbuf[t];
        __syncthreads();
        if (t == 0) carry += sbuf[1023];
        __syncthreads();
    }
}

__global__ void k_copy_int(const int* __restrict__ a, int* __restrict__ b, int n) {
    int i = blockIdx.x * blockDim.x + threadIdx.x;
    if (i < n) b[i] = a[i];
}

__global__ void k_scatter(const int* __restrict__ dst, int L, int* __restrict__ cursor,
                          int* __restrict__ eidx) {
    int i = blockIdx.x * blockDim.x + threadIdx.x;
    if (i < L) {
        int pos = atomicAdd(&cursor[dst[i]], 1);
        eidx[pos] = i;
    }
}

__global__ void k_sort_buckets(const int* __restrict__ rowptr, int* __restrict__ eidx) {
    int node = blockIdx.x * blockDim.x + threadIdx.x;
    if (node >= NN) return;
    int a = rowptr[node], b = rowptr[node + 1];
    for (int i = a + 1; i < b; i++) {
        int key = eidx[i];
        int j = i - 1;
        while (j >= a && eidx[j] > key) { eidx[j + 1] = eidx[j]; j--; }
        eidx[j + 1] = key;
    }
}

__global__ void k_half(const float* __restrict__ s, __half* __restrict__ h, int n) {
    int i = blockIdx.x * blockDim.x + threadIdx.x;
    if (i < n) h[i] = __float2half(s[i]);
}

__global__ void k_half_cat(const float* __restrict__ s, __half* __restrict__ wcat, int off) {
    int i = blockIdx.x * blockDim.x + threadIdx.x;
    if (i >= 2 * HC * FINC) return;
    int l = i >> 17;
    int rem = i & 131071;
    int rr = rem >> 8;
    int c = rem & 255;
    wcat[((l * 1024 + off + rr) << 8) + c] = __float2half(s[i]);
}

// ---------------- fused per-node edge softmax aggregation (fp16 out) -------------
__global__ __launch_bounds__(128) void k_agg(
    const float* __restrict__ sfeat, const float* __restrict__ dfeat,
    int sstr, int dstr,
    const float* __restrict__ We, const float* __restrict__ ea,
    const int* __restrict__ srcIdx, const int* __restrict__ rowptr,
    const int* __restrict__ eidx, __half* __restrict__ oh)
{
    __shared__ float wsh[HC];
    int t = threadIdx.x;
    for (int i = t; i < HC; i += 128) wsh[i] = We[i];
    __syncthreads();
    int warp = t >> 5, lane = t & 31;
    int node = blockIdx.x * 4 + warp;
    if (node >= NN) return;

    float wv[16];
#pragma unroll
    for (int j = 0; j < 16; j++) wv[j] = wsh[lane + 32 * j];

    float m[16], s[16], tt[16];
#pragma unroll
    for (int j = 0; j < 16; j++) { m[j] = -INFINITY; s[j] = 0.f; tt[j] = 0.f; }

    int e0 = rowptr[node], e1 = rowptr[node + 1];
    for (int e = e0; e < e1; e++) {
        int eid = eidx[e];
        int sidx = srcIdx[eid];
        float a = ea[eid];
        const float* row = sfeat + (size_t)sidx * sstr;
#pragma unroll
        for (int j = 0; j < 16; j++) {
            float msg = fmaxf(row[lane + 32 * j] + a * wv[j], 0.f) + 1e-7f;
            float mn = fmaxf(m[j], msg);
            float scale = __expf(m[j] - mn);
            float p = __expf(msg - mn);
            s[j] = s[j] * scale + p;
            tt[j] = tt[j] * scale + msg * p;
            m[j] = mn;
        }
    }
    const float* drow = dfeat + (size_t)node * dstr;
    __half* hrow = oh + (size_t)node * HC;
#pragma unroll
    for (int j = 0; j < 16; j++) {
        float v = tt[j] / (s[j] + 1e-16f) + drow[lane + 32 * j];
        hrow[lane + 32 * j] = __float2half(v);
    }
}

// ---------------- fp16 GEMM: 128x128x32, cp.async 4-stage, ldmatrix fragments ----
// mode 0: fp32 out (+accum). mode 1: BN+ReLU -> fp16. mode 2: fp32 leaky(old+acc).
#define BM 128
#define BN 128
#define BK 32
#define BKH 40
#define STG 4
#define TILE_B (BM * BKH * 2)
#define STAGE_B (2 * TILE_B)
#define DSMEM (STG * STAGE_B)

__device__ __forceinline__ void mma_f16(float* c, const uint32_t* a, uint32_t b0, uint32_t b1) {
    asm volatile(
        "mma.sync.aligned.m16n8k16.row.col.f32.f16.f16.f32 "
        "{%0,%1,%2,%3}, {%4,%5,%6,%7}, {%8,%9}, {%0,%1,%2,%3};"
        : "+f"(c[0]), "+f"(c[1]), "+f"(c[2]), "+f"(c[3])
        : "r"(a[0]), "r"(a[1]), "r"(a[2]), "r"(a[3]), "r"(b0), "r"(b1));
}

__device__ __forceinline__ void ldsm4(uint32_t* r, uint32_t addr) {
    asm volatile("ldmatrix.sync.aligned.m8n8.x4.shared.b16 {%0,%1,%2,%3}, [%4];"
                 : "=r"(r[0]), "=r"(r[1]), "=r"(r[2]), "=r"(r[3]) : "r"(addr));
}

__device__ __forceinline__ void cp16(uint32_t saddr, const void* gaddr, int srcbytes) {
    asm volatile("cp.async.cg.shared.global [%0], [%1], 16, %2;"
                 :: "r"(saddr), "l"(gaddr), "r"(srcbytes));
}

__global__ __launch_bounds__(256, 2) void k_hgemm(
    const __half* __restrict__ A, const __half* __restrict__ B,
    int M, int K, int Ncols, int mode,
    const float* __restrict__ gv, const float* __restrict__ bv,
    const float* __restrict__ mv, const float* __restrict__ vv,
    float* __restrict__ Cf, __half* __restrict__ Ch, int accum)
{
    extern __shared__ __align__(128) char smc[];
    uint32_t sbase = (uint32_t)__cvta_generic_to_shared(smc);

    int tid = threadIdx.x;
    int tileM = blockIdx.y * BM, tileN = blockIdx.x * BN;
    int warp = tid >> 5, lane = tid & 31;
    int g8 = lane >> 2, t4 = lane & 3;
    int wm = (warp & 1) * 64;
    int wn = (warp >> 1) * 32;

    const __half* Ag = A + (size_t)tileM * K;
    const __half* Bg = B + (size_t)tileN * K;

    // cp.async staging map (unchanged from round 6)
    int q0 = tid, q1 = tid + 256;
    int r0s = q0 >> 2, c0s = (q0 & 3) * 8;
    int r1s = q1 >> 2, c1s = (q1 & 3) * 8;
    int szA0 = (tileM + r0s) < M ? 16 : 0;
    int szA1 = (tileM + r1s) < M ? 16 : 0;
    uint32_t dA0 = sbase + (uint32_t)(r0s * (BKH * 2) + c0s * 2);
    uint32_t dA1 = sbase + (uint32_t)(r1s * (BKH * 2) + c1s * 2);
    uint32_t dB0 = dA0 + TILE_B;
    uint32_t dB1 = dA1 + TILE_B;

    // ldmatrix lane address offsets (bytes from stage base)
    // A x4: matrices {m-lo/k-lo, m-hi/k-lo, m-lo/k-hi, m-hi/k-hi}
    int mrowA = (lane & 7) + ((lane >> 3) & 1) * 8;
    int kcolA = (lane >> 4) * 8;
    uint32_t aOff = (uint32_t)(((wm + mrowA) * BKH + kcolA) * 2);
    // B x4 (two n8 groups): matrices {n-lo/k-lo, n-lo/k-hi, n-hi/k-lo, n-hi/k-hi}
    int nrowB = ((lane >> 4) & 1) * 8 + (lane & 7);
    int kcolB = ((lane >> 3) & 1) * 8;
    uint32_t bOff = (uint32_t)(TILE_B + ((wn + nrowB) * BKH + kcolB) * 2);

    float acc[4][4][4];
#pragma unroll
    for (int i = 0; i < 4; i++)
#pragma unroll
        for (int j = 0; j < 4; j++)
#pragma unroll
            for (int r = 0; r < 4; r++) acc[i][j][r] = 0.f;

    int nt = K / BK;

#define HISSUE(tile, stage)                                                     \
    do {                                                                        \
        int kb_ = (tile) * BK;                                                  \
        uint32_t so_ = (uint32_t)((stage) * STAGE_B);                           \
        cp16(dA0 + so_, Ag + (size_t)r0s * K + kb_ + c0s, szA0);                \
        cp16(dA1 + so_, Ag + (size_t)r1s * K + kb_ + c1s, szA1);                \
        cp16(dB0 + so_, Bg + (size_t)r0s * K + kb_ + c0s, 16);                  \
        cp16(dB1 + so_, Bg + (size_t)r1s * K + kb_ + c1s, 16);                  \
    } while (0)

#pragma unroll
    for (int s = 0; s < STG - 1; s++) {
        if (s < nt) HISSUE(s, s);
        asm volatile("cp.async.commit_group;");
    }

    for (int t = 0; t < nt; t++) {
        asm volatile("cp.async.wait_group %0;" :: "n"(STG - 2));
        __syncthreads();

        int ntile = t + STG - 1;
        if (ntile < nt) HISSUE(ntile, ntile & (STG - 1));
        asm volatile("cp.async.commit_group;");

        uint32_t stg = sbase + (uint32_t)((t & (STG - 1)) * STAGE_B);

#pragma unroll
        for (int kk = 0; kk < 2; kk++) {
            uint32_t kby = (uint32_t)(kk * 16 * 2);
            uint32_t af[4][4], bfr[2][4];
#pragma unroll
            for (int i = 0; i < 4; i++)
                ldsm4(af[i], stg + aOff + (uint32_t)(i * 16 * BKH * 2) + kby);
#pragma unroll
            for (int jp = 0; jp < 2; jp++)
                ldsm4(bfr[jp], stg + bOff + (uint32_t)(jp * 16 * BKH * 2) + kby);
#pragma unroll
            for (int j = 0; j < 4; j++) {
                uint32_t b0 = bfr[j >> 1][(j & 1) * 2];
                uint32_t b1 = bfr[j >> 1][(j & 1) * 2 + 1];
#pragma unroll
                for (int i = 0; i < 4; i++) mma_f16(acc[i][j], af[i], b0, b1);
            }
        }
    }

    float cs[4][2], cb[4][2], cm[4][2];
    if (mode == 1) {
#pragma unroll
        for (int j = 0; j < 4; j++) {
            int c = tileN + wn + j * 8 + t4 * 2;
#pragma unroll
            for (int q = 0; q < 2; q++) {
                cs[j][q] = gv[c + q] * rsqrtf(vv[c + q] + 1e-5f);
                cb[j][q] = bv[c + q];
                cm[j][q] = mv[c + q];
            }
        }
    }

#pragma unroll
    for (int i = 0; i < 4; i++) {
#pragma unroll
        for (int h8 = 0; h8 < 2; h8++) {
            int r = tileM + wm + i * 16 + g8 + h8 * 8;
            if (r >= M) continue;
#pragma unroll
            for (int j = 0; j < 4; j++) {
                int c = tileN + wn + j * 8 + t4 * 2;
                float v0 = acc[i][j][h8 * 2 + 0];
                float v1 = acc[i][j][h8 * 2 + 1];
                if (mode == 1) {
                    v0 = fmaxf((v0 - cm[j][0]) * cs[j][0] + cb[j][0], 0.f);
                    v1 = fmaxf((v1 - cm[j][1]) * cs[j][1] + cb[j][1], 0.f);
                    __half2 hv;
                    hv.x = __float2half(v0);
                    hv.y = __float2half(v1);
                    *(__half2*)(Ch + (size_t)r * Ncols + c) = hv;
                } else if (mode == 2) {
                    float* crow = Cf + (size_t)r * Ncols + c;
                    float2 old = *(const float2*)crow;
                    v0 += old.x;
                    v1 += old.y;
                    v0 = v0 > 0.f ? v0 : 0.01f * v0;
                    v1 = v1 > 0.f ? v1 : 0.01f * v1;
                    *(float2*)crow = make_float2(v0, v1);
                } else {
                    float* crow = Cf + (size_t)r * Ncols + c;
                    if (accum) {
                        float2 old = *(const float2*)crow;
                        v0 += old.x;
                        v1 += old.y;
                    }
                    *(float2*)crow = make_float2(v0, v1);
                }
            }
        }
    }
}

// ---------------- host orchestration (single stream) ----------------
extern "C" void kernel_launch(void* const* d_in, const int* in_sizes, int n_in,
                              void* d_out, int out_size) {
    const float* x  = (const float*)d_in[0];
    const int*   ei = (const int*)d_in[1];
    const float* ea = (const float*)d_in[2];
    int base = 3;
    if (n_in > 19) base = 3 + (n_in - 19);
    const float* l0_src  = (const float*)d_in[base + 0];
    const float* l0_dst  = (const float*)d_in[base + 1];
    const float* l0_edge = (const float*)d_in[base + 2];
    const float* l0_w1   = (const float*)d_in[base + 3];
    const float* l0_g    = (const float*)d_in[base + 4];
    const float* l0_b    = (const float*)d_in[base + 5];
    const float* l0_m    = (const float*)d_in[base + 6];
    const float* l0_v    = (const float*)d_in[base + 7];
    const float* l0_w2   = (const float*)d_in[base + 8];
    const float* l1_edge = (const float*)d_in[base + 9];
    const float* l1_w1   = (const float*)d_in[base + 10];
    const float* l1_g    = (const float*)d_in[base + 11];
    const float* l1_b    = (const float*)d_in[base + 12];
    const float* l1_m    = (const float*)d_in[base + 13];
    const float* l1_v    = (const float*)d_in[base + 14];
    const float* l1_w2   = (const float*)d_in[base + 15];
    float* out = (float*)d_out;

    float *sfdf, *yb;
    __half *xh, *ob, *hb, *wcat, *w01, *w02, *w11, *w12;
    int *rowptr, *cursor, *eidx;
    cudaGetSymbolAddress((void**)&sfdf, g_sfdf);
    cudaGetSymbolAddress((void**)&yb, g_y);
    cudaGetSymbolAddress((void**)&xh, g_xh);
    cudaGetSymbolAddress((void**)&ob, g_ob);
    cudaGetSymbolAddress((void**)&hb, g_hb);
    cudaGetSymbolAddress((void**)&wcat, g_wcat);
    cudaGetSymbolAddress((void**)&w01, g_w01);
    cudaGetSymbolAddress((void**)&w02, g_w02);
    cudaGetSymbolAddress((void**)&w11, g_w11);
    cudaGetSymbolAddress((void**)&w12, g_w12);
    cudaGetSymbolAddress((void**)&rowptr, g_rowptr);
    cudaGetSymbolAddress((void**)&cursor, g_cursor);
    cudaGetSymbolAddress((void**)&eidx, g_eidx);

    cudaFuncSetAttribute(k_hgemm, cudaFuncAttributeMaxDynamicSharedMemorySize, DSMEM);

    const int offs[2] = {0, LPART};

    // ---- fp16 operand conversion ----
    k_half<<<(NN * FINC + 255) / 256, 256>>>(x, xh, NN * FINC);
    k_half_cat<<<(2 * HC * FINC + 255) / 256, 256>>>(l0_src, wcat, 0);
    k_half_cat<<<(2 * HC * FINC + 255) / 256, 256>>>(l0_dst, wcat, 512);
    k_half<<<(2 * H2C * HC + 255) / 256, 256>>>(l0_w1, w01, 2 * H2C * HC);
    k_half<<<(2 * HC * H2C + 255) / 256, 256>>>(l0_w2, w02, 2 * HC * H2C);
    k_half<<<(2 * H2C * HC + 255) / 256, 256>>>(l1_w1, w11, 2 * H2C * HC);
    k_half<<<(2 * HC * H2C + 255) / 256, 256>>>(l1_w2, w12, 2 * HC * H2C);

    // ---- CSR build ----
    for (int p = 0; p < 2; p++) {
        int* rp = rowptr + p * (NN + 1);
        int* cu = cursor + p * NN;
        int* ex = eidx + p * LPART;
        const int* dstp = ei + ETOT + offs[p];
        k_zero_int<<<(NN + 255) / 256, 256>>>(cu, NN);
        k_count_deg<<<(LPART + 255) / 256, 256>>>(dstp, LPART, cu);
        k_scan<<<1, 1024>>>(cu, rp, NN);
        k_copy_int<<<(NN + 255) / 256, 256>>>(rp, cu, NN);
        k_scatter<<<(LPART + 255) / 256, 256>>>(dstp, LPART, cu, ex);
        k_sort_buckets<<<(NN + 127) / 128, 128>>>(rp, ex);
    }

    dim3 blk(256);
    int gy = (NN + BM - 1) / BM;
    dim3 gproj(2048 / BN, gy), g512(HC / BN, gy), g1024(H2C / BN, gy);

    // ---- layer 0: merged projection GEMM ----
    k_hgemm<<<gproj, blk, DSMEM>>>(xh, wcat, NN, FINC, 2048, 0,
                                   nullptr, nullptr, nullptr, nullptr, sfdf, nullptr, 0);

    for (int l = 0; l < 2; l++) {
        k_agg<<<(NN + 3) / 4, 128>>>(sfdf + l * 1024, sfdf + l * 1024 + 512, 2048, 2048,
                                     l0_edge + (size_t)l * HC, ea + offs[l],
                                     ei + offs[l], rowptr + l * (NN + 1),
                                     eidx + l * LPART, ob);
        k_hgemm<<<g1024, blk, DSMEM>>>(ob, w01 + (size_t)l * H2C * HC,
                                       NN, HC, H2C, 1,
                                       l0_g + l * H2C, l0_b + l * H2C,
                                       l0_m + l * H2C, l0_v + l * H2C,
                                       nullptr, hb, 0);
        // l=0: plain store to yb; l=1: fused accumulate + leaky (x1 := leaky(yb+acc))
        k_hgemm<<<g512, blk, DSMEM>>>(hb, w02 + (size_t)l * HC * H2C,
                                      NN, H2C, HC, l == 0 ? 0 : 2,
                                      nullptr, nullptr, nullptr, nullptr,
                                      yb, nullptr, 0);
    }

    // ---- layer 1 (sf = df = yb, stride 512) ----
    for (int l = 0; l < 2; l++) {
        k_agg<<<(NN + 3) / 4, 128>>>(yb, yb, HC, HC,
                                     l1_edge + (size_t)l * HC, ea + offs[l],
                                     ei + offs[l], rowptr + l * (NN + 1),
                                     eidx + l * LPART, ob);
        k_hgemm<<<g1024, blk, DSMEM>>>(ob, w11 + (size_t)l * H2C * HC,
                                       NN, HC, H2C, 1,
                                       l1_g + l * H2C, l1_b + l * H2C,
                                       l1_m + l * H2C, l1_v + l * H2C,
                                       nullptr, hb, 0);
        k_hgemm<<<g512, blk, DSMEM>>>(hb, w12 + (size_t)l * HC * H2C,
                                      NN, H2C, HC, 0,
                                      nullptr, nullptr, nullptr, nullptr,
                                      out, nullptr, l > 0);
    }
}

// round 10
// speedup vs baseline: 1.4588x; 1.0530x over previous
#include <cuda_runtime.h>
#include <cuda_fp16.h>
#include <math.h>
#include <stdint.h>

#define NN 20000
#define ETOT 150000
#define LPART 75000
#define FINC 256
#define HC 512
#define H2C 1024

// ---------------- static device scratch ----------------
__device__ __half g_sfdf[NN * 2048];  // layer0 merged projections (fp16)
__device__ float g_y[NN * HC];        // y, then x1 (leaky fused in-place)
__device__ __half g_xh[NN * FINC];
__device__ __half g_ob[NN * HC];
__device__ __half g_hb[NN * H2C];
__device__ __half g_wcat[2048 * FINC];
__device__ __half g_w01[2 * H2C * HC], g_w02[2 * HC * H2C];
__device__ __half g_w11[2 * H2C * HC], g_w12[2 * HC * H2C];
__device__ int g_rowptr[2][NN + 1];
__device__ int g_cursor[2][NN];
__device__ int g_eidx[2][LPART];

// ---------------- CSR build (both partitions fused per launch) ----------------
__global__ void k_zero_int(int* p, int n) {
    int i = blockIdx.x * blockDim.x + threadIdx.x;
    if (i < n) p[i] = 0;
}

// dst arrays for p0,p1 are contiguous: ei[ETOT .. ETOT+2*LPART)
__global__ void k_count_deg2(const int* __restrict__ dstBoth, int* __restrict__ deg) {
    int i = blockIdx.x * blockDim.x + threadIdx.x;
    if (i < 2 * LPART) {
        int p = i / LPART;
        atomicAdd(&deg[p * NN + dstBoth[i]], 1);
    }
}

// 2 blocks: block p scans partition p
__global__ void k_scan2(const int* __restrict__ deg, int* __restrict__ rowptr) {
    __shared__ int sbuf[1024];
    __shared__ int carry;
    int p = blockIdx.x;
    const int* d = deg + p * NN;
    int* rp = rowptr + p * (NN + 1);
    int t = threadIdx.x;
    if (t == 0) { carry = 0; rp[0] = 0; }
    __syncthreads();
    for (int base = 0; base < NN; base += 1024) {
        int v = (base + t < NN) ? d[base + t] : 0;
        sbuf[t] = v;
        __syncthreads();
        for (int off = 1; off < 1024; off <<= 1) {
            int nv = (t >= off) ? sbuf[t - off] : 0;
            __syncthreads();
            sbuf[t] += nv;
            __syncthreads();
        }
        if (base + t < NN) rp[base + t + 1] = carry + sbuf[t];
        __syncthreads();
        if (t == 0) carry += sbuf[1023];
        __syncthreads();
    }
}

__global__ void k_copy_rp2(const int* __restrict__ rowptr, int* __restrict__ cursor) {
    int i = blockIdx.x * blockDim.x + threadIdx.x;
    if (i < 2 * NN) {
        int p = i / NN, r = i % NN;
        cursor[i] = rowptr[p * (NN + 1) + r];
    }
}

__global__ void k_scatter2(const int* __restrict__ dstBoth, int* __restrict__ cursor,
                           int* __restrict__ eidx) {
    int i = blockIdx.x * blockDim.x + threadIdx.x;
    if (i < 2 * LPART) {
        int p = i / LPART;
        int pos = atomicAdd(&cursor[p * NN + dstBoth[i]], 1);
        eidx[p * LPART + pos] = i - p * LPART;
    }
}

__global__ void k_sort_buckets2(const int* __restrict__ rowptr, int* __restrict__ eidx) {
    int i = blockIdx.x * blockDim.x + threadIdx.x;
    if (i >= 2 * NN) return;
    int p = i / NN, node = i % NN;
    const int* rp = rowptr + p * (NN + 1);
    int* ex = eidx + p * LPART;
    int a = rp[node], b = rp[node + 1];
    for (int q = a + 1; q < b; q++) {
        int key = ex[q];
        int j = q - 1;
        while (j >= a && ex[j] > key) { ex[j + 1] = ex[j]; j--; }
        ex[j + 1] = key;
    }
}

__global__ void k_half(const float* __restrict__ s, __half* __restrict__ h, int n) {
    int i = blockIdx.x * blockDim.x + threadIdx.x;
    if (i < n) h[i] = __float2half(s[i]);
}

__global__ void k_half_cat(const float* __restrict__ s, __half* __restrict__ wcat, int off) {
    int i = blockIdx.x * blockDim.x + threadIdx.x;
    if (i >= 2 * HC * FINC) return;
    int l = i >> 17;
    int rem = i & 131071;
    int rr = rem >> 8;
    int c = rem & 255;
    wcat[((l * 1024 + off + rr) << 8) + c] = __float2half(s[i]);
}

// ---------------- fused per-node edge softmax aggregation (fp16 out) -------------
template <typename TS>
__global__ __launch_bounds__(128) void k_agg(
    const TS* __restrict__ sfeat, const TS* __restrict__ dfeat,
    int sstr, int dstr,
    const float* __restrict__ We, const float* __restrict__ ea,
    const int* __restrict__ srcIdx, const int* __restrict__ rowptr,
    const int* __restrict__ eidx, __half* __restrict__ oh)
{
    __shared__ float wsh[HC];
    int t = threadIdx.x;
    for (int i = t; i < HC; i += 128) wsh[i] = We[i];
    __syncthreads();
    int warp = t >> 5, lane = t & 31;
    int node = blockIdx.x * 4 + warp;
    if (node >= NN) return;

    float wv[16];
#pragma unroll
    for (int j = 0; j < 16; j++) wv[j] = wsh[lane + 32 * j];

    float m[16], s[16], tt[16];
#pragma unroll
    for (int j = 0; j < 16; j++) { m[j] = -INFINITY; s[j] = 0.f; tt[j] = 0.f; }

    int e0 = rowptr[node], e1 = rowptr[node + 1];
    for (int e = e0; e < e1; e++) {
        int eid = eidx[e];
        int sidx = srcIdx[eid];
        float a = ea[eid];
        const TS* row = sfeat + (size_t)sidx * sstr;
#pragma unroll
        for (int j = 0; j < 16; j++) {
            float msg = fmaxf((float)row[lane + 32 * j] + a * wv[j], 0.f) + 1e-7f;
            float mn = fmaxf(m[j], msg);
            float scale = __expf(m[j] - mn);
            float p = __expf(msg - mn);
            s[j] = s[j] * scale + p;
            tt[j] = tt[j] * scale + msg * p;
            m[j] = mn;
        }
    }
    const TS* drow = dfeat + (size_t)node * dstr;
    __half* hrow = oh + (size_t)node * HC;
#pragma unroll
    for (int j = 0; j < 16; j++) {
        float v = tt[j] / (s[j] + 1e-16f) + (float)drow[lane + 32 * j];
        hrow[lane + 32 * j] = __float2half(v);
    }
}

// ---------------- fp16 GEMM: 128x128x32, cp.async 4-stage, ldmatrix fragments ----
// mode 0: fp32 out (+accum). mode 1: BN+ReLU -> fp16. mode 2: fp32 leaky(old+acc).
// mode 3: plain fp16 out.
#define BM 128
#define BN 128
#define BK 32
#define BKH 40
#define STG 4
#define TILE_B (BM * BKH * 2)
#define STAGE_B (2 * TILE_B)
#define DSMEM (STG * STAGE_B)

__device__ __forceinline__ void mma_f16(float* c, const uint32_t* a, uint32_t b0, uint32_t b1) {
    asm volatile(
        "mma.sync.aligned.m16n8k16.row.col.f32.f16.f16.f32 "
        "{%0,%1,%2,%3}, {%4,%5,%6,%7}, {%8,%9}, {%0,%1,%2,%3};"
        : "+f"(c[0]), "+f"(c[1]), "+f"(c[2]), "+f"(c[3])
        : "r"(a[0]), "r"(a[1]), "r"(a[2]), "r"(a[3]), "r"(b0), "r"(b1));
}

__device__ __forceinline__ void ldsm4(uint32_t* r, uint32_t addr) {
    asm volatile("ldmatrix.sync.aligned.m8n8.x4.shared.b16 {%0,%1,%2,%3}, [%4];"
                 : "=r"(r[0]), "=r"(r[1]), "=r"(r[2]), "=r"(r[3]) : "r"(addr));
}

__device__ __forceinline__ void cp16(uint32_t saddr, const void* gaddr, int srcbytes) {
    asm volatile("cp.async.cg.shared.global [%0], [%1], 16, %2;"
                 :: "r"(saddr), "l"(gaddr), "r"(srcbytes));
}

__global__ __launch_bounds__(256, 2) void k_hgemm(
    const __half* __restrict__ A, const __half* __restrict__ B,
    int M, int K, int Ncols, int mode,
    const float* __restrict__ gv, const float* __restrict__ bv,
    const float* __restrict__ mv, const float* __restrict__ vv,
    float* __restrict__ Cf, __half* __restrict__ Ch, int accum)
{
    extern __shared__ __align__(128) char smc[];
    uint32_t sbase = (uint32_t)__cvta_generic_to_shared(smc);

    int tid = threadIdx.x;
    int tileM = blockIdx.y * BM, tileN = blockIdx.x * BN;
    int warp = tid >> 5, lane = tid & 31;
    int g8 = lane >> 2, t4 = lane & 3;
    int wm = (warp & 1) * 64;
    int wn = (warp >> 1) * 32;

    const __half* Ag = A + (size_t)tileM * K;
    const __half* Bg = B + (size_t)tileN * K;

    int q0 = tid, q1 = tid + 256;
    int r0s = q0 >> 2, c0s = (q0 & 3) * 8;
    int r1s = q1 >> 2, c1s = (q1 & 3) * 8;
    int szA0 = (tileM + r0s) < M ? 16 : 0;
    int szA1 = (tileM + r1s) < M ? 16 : 0;
    uint32_t dA0 = sbase + (uint32_t)(r0s * (BKH * 2) + c0s * 2);
    uint32_t dA1 = sbase + (uint32_t)(r1s * (BKH * 2) + c1s * 2);
    uint32_t dB0 = dA0 + TILE_B;
    uint32_t dB1 = dA1 + TILE_B;

    int mrowA = (lane & 7) + ((lane >> 3) & 1) * 8;
    int kcolA = (lane >> 4) * 8;
    uint32_t aOff = (uint32_t)(((wm + mrowA) * BKH + kcolA) * 2);
    int nrowB = ((lane >> 4) & 1) * 8 + (lane & 7);
    int kcolB = ((lane >> 3) & 1) * 8;
    uint32_t bOff = (uint32_t)(TILE_B + ((wn + nrowB) * BKH + kcolB) * 2);

    float acc[4][4][4];
#pragma unroll
    for (int i = 0; i < 4; i++)
#pragma unroll
        for (int j = 0; j < 4; j++)
#pragma unroll
            for (int r = 0; r < 4; r++) acc[i][j][r] = 0.f;

    int nt = K / BK;

#define HISSUE(tile, stage)                                                     \
    do {                                                                        \
        int kb_ = (tile) * BK;                                                  \
        uint32_t so_ = (uint32_t)((stage) * STAGE_B);                           \
        cp16(dA0 + so_, Ag + (size_t)r0s * K + kb_ + c0s, szA0);                \
        cp16(dA1 + so_, Ag + (size_t)r1s * K + kb_ + c1s, szA1);                \
        cp16(dB0 + so_, Bg + (size_t)r0s * K + kb_ + c0s, 16);                  \
        cp16(dB1 + so_, Bg + (size_t)r1s * K + kb_ + c1s, 16);                  \
    } while (0)

#pragma unroll
    for (int s = 0; s < STG - 1; s++) {
        if (s < nt) HISSUE(s, s);
        asm volatile("cp.async.commit_group;");
    }

    for (int t = 0; t < nt; t++) {
        asm volatile("cp.async.wait_group %0;" :: "n"(STG - 2));
        __syncthreads();

        int ntile = t + STG - 1;
        if (ntile < nt) HISSUE(ntile, ntile & (STG - 1));
        asm volatile("cp.async.commit_group;");

        uint32_t stg = sbase + (uint32_t)((t & (STG - 1)) * STAGE_B);

#pragma unroll
        for (int kk = 0; kk < 2; kk++) {
            uint32_t kby = (uint32_t)(kk * 16 * 2);
            uint32_t af[4][4], bfr[2][4];
#pragma unroll
            for (int i = 0; i < 4; i++)
                ldsm4(af[i], stg + aOff + (uint32_t)(i * 16 * BKH * 2) + kby);
#pragma unroll
            for (int jp = 0; jp < 2; jp++)
                ldsm4(bfr[jp], stg + bOff + (uint32_t)(jp * 16 * BKH * 2) + kby);
#pragma unroll
            for (int j = 0; j < 4; j++) {
                uint32_t b0 = bfr[j >> 1][(j & 1) * 2];
                uint32_t b1 = bfr[j >> 1][(j & 1) * 2 + 1];
#pragma unroll
                for (int i = 0; i < 4; i++) mma_f16(acc[i][j], af[i], b0, b1);
            }
        }
    }

    float cs[4][2], cb[4][2], cm[4][2];
    if (mode == 1) {
#pragma unroll
        for (int j = 0; j < 4; j++) {
            int c = tileN + wn + j * 8 + t4 * 2;
#pragma unroll
            for (int q = 0; q < 2; q++) {
                cs[j][q] = gv[c + q] * rsqrtf(vv[c + q] + 1e-5f);
                cb[j][q] = bv[c + q];
                cm[j][q] = mv[c + q];
            }
        }
    }

#pragma unroll
    for (int i = 0; i < 4; i++) {
#pragma unroll
        for (int h8 = 0; h8 < 2; h8++) {
            int r = tileM + wm + i * 16 + g8 + h8 * 8;
            if (r >= M) continue;
#pragma unroll
            for (int j = 0; j < 4; j++) {
                int c = tileN + wn + j * 8 + t4 * 2;
                float v0 = acc[i][j][h8 * 2 + 0];
                float v1 = acc[i][j][h8 * 2 + 1];
                if (mode == 1) {
                    v0 = fmaxf((v0 - cm[j][0]) * cs[j][0] + cb[j][0], 0.f);
                    v1 = fmaxf((v1 - cm[j][1]) * cs[j][1] + cb[j][1], 0.f);
                    __half2 hv;
                    hv.x = __float2half(v0);
                    hv.y = __float2half(v1);
                    *(__half2*)(Ch + (size_t)r * Ncols + c) = hv;
                } else if (mode == 3) {
                    __half2 hv;
                    hv.x = __float2half(v0);
                    hv.y = __float2half(v1);
                    *(__half2*)(Ch + (size_t)r * Ncols + c) = hv;
                } else if (mode == 2) {
                    float* crow = Cf + (size_t)r * Ncols + c;
                    float2 old = *(const float2*)crow;
                    v0 += old.x;
                    v1 += old.y;
                    v0 = v0 > 0.f ? v0 : 0.01f * v0;
                    v1 = v1 > 0.f ? v1 : 0.01f * v1;
                    *(float2*)crow = make_float2(v0, v1);
                } else {
                    float* crow = Cf + (size_t)r * Ncols + c;
                    if (accum) {
                        float2 old = *(const float2*)crow;
                        v0 += old.x;
                        v1 += old.y;
                    }
                    *(float2*)crow = make_float2(v0, v1);
                }
            }
        }
    }
}

// ---------------- host orchestration (single stream) ----------------
extern "C" void kernel_launch(void* const* d_in, const int* in_sizes, int n_in,
                              void* d_out, int out_size) {
    const float* x  = (const float*)d_in[0];
    const int*   ei = (const int*)d_in[1];
    const float* ea = (const float*)d_in[2];
    int base = 3;
    if (n_in > 19) base = 3 + (n_in - 19);
    const float* l0_src  = (const float*)d_in[base + 0];
    const float* l0_dst  = (const float*)d_in[base + 1];
    const float* l0_edge = (const float*)d_in[base + 2];
    const float* l0_w1   = (const float*)d_in[base + 3];
    const float* l0_g    = (const float*)d_in[base + 4];
    const float* l0_b    = (const float*)d_in[base + 5];
    const float* l0_m    = (const float*)d_in[base + 6];
    const float* l0_v    = (const float*)d_in[base + 7];
    const float* l0_w2   = (const float*)d_in[base + 8];
    const float* l1_edge = (const float*)d_in[base + 9];
    const float* l1_w1   = (const float*)d_in[base + 10];
    const float* l1_g    = (const float*)d_in[base + 11];
    const float* l1_b    = (const float*)d_in[base + 12];
    const float* l1_m    = (const float*)d_in[base + 13];
    const float* l1_v    = (const float*)d_in[base + 14];
    const float* l1_w2   = (const float*)d_in[base + 15];
    float* out = (float*)d_out;

    float *yb;
    __half *sfdf, *xh, *ob, *hb, *wcat, *w01, *w02, *w11, *w12;
    int *rowptr, *cursor, *eidx;
    cudaGetSymbolAddress((void**)&sfdf, g_sfdf);
    cudaGetSymbolAddress((void**)&yb, g_y);
    cudaGetSymbolAddress((void**)&xh, g_xh);
    cudaGetSymbolAddress((void**)&ob, g_ob);
    cudaGetSymbolAddress((void**)&hb, g_hb);
    cudaGetSymbolAddress((void**)&wcat, g_wcat);
    cudaGetSymbolAddress((void**)&w01, g_w01);
    cudaGetSymbolAddress((void**)&w02, g_w02);
    cudaGetSymbolAddress((void**)&w11, g_w11);
    cudaGetSymbolAddress((void**)&w12, g_w12);
    cudaGetSymbolAddress((void**)&rowptr, g_rowptr);
    cudaGetSymbolAddress((void**)&cursor, g_cursor);
    cudaGetSymbolAddress((void**)&eidx, g_eidx);

    cudaFuncSetAttribute(k_hgemm, cudaFuncAttributeMaxDynamicSharedMemorySize, DSMEM);

    const int offs[2] = {0, LPART};
    const int* dstBoth = ei + ETOT;

    // ---- fp16 operand conversion ----
    k_half<<<(NN * FINC + 255) / 256, 256>>>(x, xh, NN * FINC);
    k_half_cat<<<(2 * HC * FINC + 255) / 256, 256>>>(l0_src, wcat, 0);
    k_half_cat<<<(2 * HC * FINC + 255) / 256, 256>>>(l0_dst, wcat, 512);
    k_half<<<(2 * H2C * HC + 255) / 256, 256>>>(l0_w1, w01, 2 * H2C * HC);
    k_half<<<(2 * HC * H2C + 255) / 256, 256>>>(l0_w2, w02, 2 * HC * H2C);
    k_half<<<(2 * H2C * HC + 255) / 256, 256>>>(l1_w1, w11, 2 * H2C * HC);
    k_half<<<(2 * HC * H2C + 255) / 256, 256>>>(l1_w2, w12, 2 * HC * H2C);

    // ---- CSR build (both partitions per launch) ----
    k_zero_int<<<(2 * NN + 255) / 256, 256>>>(cursor, 2 * NN);
    k_count_deg2<<<(2 * LPART + 255) / 256, 256>>>(dstBoth, cursor);
    k_scan2<<<2, 1024>>>(cursor, rowptr);
    k_copy_rp2<<<(2 * NN + 255) / 256, 256>>>(rowptr, cursor);
    k_scatter2<<<(2 * LPART + 255) / 256, 256>>>(dstBoth, cursor, eidx);
    k_sort_buckets2<<<(2 * NN + 127) / 128, 128>>>(rowptr, eidx);

    dim3 blk(256);
    int gy = (NN + BM - 1) / BM;
    dim3 gproj(2048 / BN, gy), g512(HC / BN, gy), g1024(H2C / BN, gy);

    // ---- layer 0: merged projection GEMM (fp16 out) ----
    k_hgemm<<<gproj, blk, DSMEM>>>(xh, wcat, NN, FINC, 2048, 3,
                                   nullptr, nullptr, nullptr, nullptr, nullptr, sfdf, 0);

    for (int l = 0; l < 2; l++) {
        k_agg<__half><<<(NN + 3) / 4, 128>>>(sfdf + l * 1024, sfdf + l * 1024 + 512,
                                             2048, 2048,
                                             l0_edge + (size_t)l * HC, ea + offs[l],
                                             ei + offs[l], rowptr + l * (NN + 1),
                                             eidx + l * LPART, ob);
        k_hgemm<<<g1024, blk, DSMEM>>>(ob, w01 + (size_t)l * H2C * HC,
                                       NN, HC, H2C, 1,
                                       l0_g + l * H2C, l0_b + l * H2C,
                                       l0_m + l * H2C, l0_v + l * H2C,
                                       nullptr, hb, 0);
        k_hgemm<<<g512, blk, DSMEM>>>(hb, w02 + (size_t)l * HC * H2C,
                                      NN, H2C, HC, l == 0 ? 0 : 2,
                                      nullptr, nullptr, nullptr, nullptr,
                                      yb, nullptr, 0);
    }

    // ---- layer 1 (sf = df = yb fp32, stride 512) ----
    for (int l = 0; l < 2; l++) {
        k_agg<float><<<(NN + 3) / 4, 128>>>(yb, yb, HC, HC,
                                            l1_edge + (size_t)l * HC, ea + offs[l],
                                            ei + offs[l], rowptr + l * (NN + 1),
                                            eidx + l * LPART, ob);
        k_hgemm<<<g1024, blk, DSMEM>>>(ob, w11 + (size_t)l * H2C * HC,
                                       NN, HC, H2C, 1,
                                       l1_g + l * H2C, l1_b + l * H2C,
                                       l1_m + l * H2C, l1_v + l * H2C,
                                       nullptr, hb, 0);
        k_hgemm<<<g512, blk, DSMEM>>>(hb, w12 + (size_t)l * HC * H2C,
                                      NN, H2C, HC, 0,
                                      nullptr, nullptr, nullptr, nullptr,
                                      out, nullptr, l > 0);
    }
}

// round 11
// speedup vs baseline: 1.5842x; 1.0860x over previous
#include <cuda_runtime.h>
#include <cuda_fp16.h>
#include <math.h>
#include <stdint.h>

#define NN 20000
#define ETOT 150000
#define LPART 75000
#define FINC 256
#define HC 512
#define H2C 1024

// ---------------- static device scratch ----------------
__device__ __half g_sfdf[NN * 2048];   // layer0 merged projections (fp16)
__device__ __half g_x1[NN * HC];       // leaky output (fp16)
__device__ __half g_xh[NN * FINC];
__device__ __half g_ob[2 * NN * HC];   // per-link agg outputs
__device__ __half g_hb[NN * 2048];     // merged W1 outputs [NN][l*1024+..]
__device__ __half g_wcat[2048 * FINC];
__device__ __half g_w01[2 * H2C * HC];        // [l*1024+n][k] (contiguous as given)
__device__ __half g_w02c[HC * 2048];          // [n][l*1024+kk] (K-concat)
__device__ __half g_w11[2 * H2C * HC];
__device__ __half g_w12c[HC * 2048];
__device__ int g_rowptr[2][NN + 1];
__device__ int g_cursor[2][NN];
__device__ int g_eidx[2][LPART];

// ---------------- CSR build (both partitions fused per launch) ----------------
__global__ void k_zero_int(int* p, int n) {
    int i = blockIdx.x * blockDim.x + threadIdx.x;
    if (i < n) p[i] = 0;
}

__global__ void k_count_deg2(const int* __restrict__ dstBoth, int* __restrict__ deg) {
    int i = blockIdx.x * blockDim.x + threadIdx.x;
    if (i < 2 * LPART) {
        int p = i / LPART;
        atomicAdd(&deg[p * NN + dstBoth[i]], 1);
    }
}

__global__ void k_scan2(const int* __restrict__ deg, int* __restrict__ rowptr) {
    __shared__ int sbuf[1024];
    __shared__ int carry;
    int p = blockIdx.x;
    const int* d = deg + p * NN;
    int* rp = rowptr + p * (NN + 1);
    int t = threadIdx.x;
    if (t == 0) { carry = 0; rp[0] = 0; }
    __syncthreads();
    for (int base = 0; base < NN; base += 1024) {
        int v = (base + t < NN) ? d[base + t] : 0;
        sbuf[t] = v;
        __syncthreads();
        for (int off = 1; off < 1024; off <<= 1) {
            int nv = (t >= off) ? sbuf[t - off] : 0;
            __syncthreads();
            sbuf[t] += nv;
            __syncthreads();
        }
        if (base + t < NN) rp[base + t + 1] = carry + sbuf[t];
        __syncthreads();
        if (t == 0) carry += sbuf[1023];
        __syncthreads();
    }
}

__global__ void k_copy_rp2(const int* __restrict__ rowptr, int* __restrict__ cursor) {
    int i = blockIdx.x * blockDim.x + threadIdx.x;
    if (i < 2 * NN) {
        int p = i / NN, r = i % NN;
        cursor[i] = rowptr[p * (NN + 1) + r];
    }
}

__global__ void k_scatter2(const int* __restrict__ dstBoth, int* __restrict__ cursor,
                           int* __restrict__ eidx) {
    int i = blockIdx.x * blockDim.x + threadIdx.x;
    if (i < 2 * LPART) {
        int p = i / LPART;
        int pos = atomicAdd(&cursor[p * NN + dstBoth[i]], 1);
        eidx[p * LPART + pos] = i - p * LPART;
    }
}

__global__ void k_sort_buckets2(const int* __restrict__ rowptr, int* __restrict__ eidx) {
    int i = blockIdx.x * blockDim.x + threadIdx.x;
    if (i >= 2 * NN) return;
    int p = i / NN, node = i % NN;
    const int* rp = rowptr + p * (NN + 1);
    int* ex = eidx + p * LPART;
    int a = rp[node], b = rp[node + 1];
    for (int q = a + 1; q < b; q++) {
        int key = ex[q];
        int j = q - 1;
        while (j >= a && ex[j] > key) { ex[j + 1] = ex[j]; j--; }
        ex[j + 1] = key;
    }
}

__global__ void k_half(const float* __restrict__ s, __half* __restrict__ h, int n) {
    int i = blockIdx.x * blockDim.x + threadIdx.x;
    if (i < n) h[i] = __float2half(s[i]);
}

__global__ void k_half_cat(const float* __restrict__ s, __half* __restrict__ wcat, int off) {
    int i = blockIdx.x * blockDim.x + threadIdx.x;
    if (i >= 2 * HC * FINC) return;
    int l = i >> 17;
    int rem = i & 131071;
    int rr = rem >> 8;
    int c = rem & 255;
    wcat[((l * 1024 + off + rr) << 8) + c] = __float2half(s[i]);
}

// W2 K-concat: in [2][512][1024] -> out[n][l*1024+kk]
__global__ void k_half_w2cat(const float* __restrict__ s, __half* __restrict__ w) {
    int i = blockIdx.x * blockDim.x + threadIdx.x;
    if (i >= 2 * HC * H2C) return;
    int l = i >> 19;
    int rem = i & 524287;
    int n = rem >> 10;
    int kk = rem & 1023;
    w[n * 2048 + (l << 10) + kk] = __float2half(s[i]);
}

// ---------------- merged per-layer edge softmax aggregation (all fp16) -----------
// one launch covers both links: warp gw in [0, 2*NN), p = gw/NN (NN%4==0 -> block-uniform)
__global__ __launch_bounds__(128) void k_agg2(
    const __half* __restrict__ sf_base, int sf_loff, int sstr,
    const __half* __restrict__ df_base, int df_loff, int dstr,
    const float* __restrict__ WeBoth,   // [2][512]
    const float* __restrict__ ea,       // [2*LPART]
    const int* __restrict__ srcBoth,    // ei rows: src at +p*LPART
    const int* __restrict__ rowptr,     // [2][NN+1]
    const int* __restrict__ eidx,       // [2][LPART]
    __half* __restrict__ oh)            // [2][NN][512]
{
    __shared__ float wsh[HC];
    int t = threadIdx.x;
    int pblk = (blockIdx.x * 4) / NN;
    for (int i = t; i < HC; i += 128) wsh[i] = WeBoth[pblk * HC + i];
    __syncthreads();

    int warp = t >> 5, lane = t & 31;
    int gw = blockIdx.x * 4 + warp;
    if (gw >= 2 * NN) return;
    int p = gw >= NN;
    int node = gw - p * NN;

    const __half2* sfeat = (const __half2*)(sf_base + (size_t)p * sf_loff);
    const __half2* dfeat = (const __half2*)(df_base + (size_t)p * df_loff);
    int s2 = sstr >> 1, d2 = dstr >> 1;
    const float* eap = ea + (size_t)p * LPART;
    const int* srcp = srcBoth + (size_t)p * LPART;
    const int* rp = rowptr + p * (NN + 1);
    const int* ex = eidx + (size_t)p * LPART;

    float wv[16];
#pragma unroll
    for (int jj = 0; jj < 8; jj++) {
        int q = lane + 32 * jj;
        wv[2 * jj] = wsh[2 * q];
        wv[2 * jj + 1] = wsh[2 * q + 1];
    }

    float m[16], s[16], tt[16];
#pragma unroll
    for (int j = 0; j < 16; j++) { m[j] = -INFINITY; s[j] = 0.f; tt[j] = 0.f; }

    int e0 = rp[node], e1 = rp[node + 1];
    for (int e = e0; e < e1; e++) {
        int eid = ex[e];
        int sidx = srcp[eid];
        float a = eap[eid];
        const __half2* row = sfeat + (size_t)sidx * s2;
#pragma unroll
        for (int jj = 0; jj < 8; jj++) {
            float2 v = __half22float2(row[lane + 32 * jj]);
#pragma unroll
            for (int h = 0; h < 2; h++) {
                int j = 2 * jj + h;
                float msg = fmaxf((h ? v.y : v.x) + a * wv[j], 0.f) + 1e-7f;
                float mn = fmaxf(m[j], msg);
                float scale = __expf(m[j] - mn);
                float pr = __expf(msg - mn);
                s[j] = s[j] * scale + pr;
                tt[j] = tt[j] * scale + msg * pr;
                m[j] = mn;
            }
        }
    }
    const __half2* drow = dfeat + (size_t)node * d2;
    __half2* hrow = (__half2*)(oh + ((size_t)p * NN + node) * HC);
#pragma unroll
    for (int jj = 0; jj < 8; jj++) {
        float2 dv = __half22float2(drow[lane + 32 * jj]);
        float o0 = tt[2 * jj] / (s[2 * jj] + 1e-16f) + dv.x;
        float o1 = tt[2 * jj + 1] / (s[2 * jj + 1] + 1e-16f) + dv.y;
        hrow[lane + 32 * jj] = __floats2half2_rn(o0, o1);
    }
}

// ---------------- fp16 GEMM: 128x128x32, cp.async 4-stage, ldmatrix --------------
// dual-A: blocks with tileN >= nsplit read A1 (B row = global tileN always).
// mode 0: fp32 store. mode 1: BN+ReLU -> fp16. mode 2: leaky -> fp16. mode 3: fp16.
#define BM 128
#define BN 128
#define BK 32
#define BKH 40
#define STG 4
#define TILE_B (BM * BKH * 2)
#define STAGE_B (2 * TILE_B)
#define DSMEM (STG * STAGE_B)

__device__ __forceinline__ void mma_f16(float* c, const uint32_t* a, uint32_t b0, uint32_t b1) {
    asm volatile(
        "mma.sync.aligned.m16n8k16.row.col.f32.f16.f16.f32 "
        "{%0,%1,%2,%3}, {%4,%5,%6,%7}, {%8,%9}, {%0,%1,%2,%3};"
        : "+f"(c[0]), "+f"(c[1]), "+f"(c[2]), "+f"(c[3])
        : "r"(a[0]), "r"(a[1]), "r"(a[2]), "r"(a[3]), "r"(b0), "r"(b1));
}

__device__ __forceinline__ void ldsm4(uint32_t* r, uint32_t addr) {
    asm volatile("ldmatrix.sync.aligned.m8n8.x4.shared.b16 {%0,%1,%2,%3}, [%4];"
                 : "=r"(r[0]), "=r"(r[1]), "=r"(r[2]), "=r"(r[3]) : "r"(addr));
}

__device__ __forceinline__ void cp16(uint32_t saddr, const void* gaddr, int srcbytes) {
    asm volatile("cp.async.cg.shared.global [%0], [%1], 16, %2;"
                 :: "r"(saddr), "l"(gaddr), "r"(srcbytes));
}

__global__ __launch_bounds__(256, 2) void k_hgemm(
    const __half* __restrict__ A0, const __half* __restrict__ A1, int nsplit,
    const __half* __restrict__ B,
    int M, int K, int Ncols, int mode,
    const float* __restrict__ gv, const float* __restrict__ bv,
    const float* __restrict__ mv, const float* __restrict__ vv,
    float* __restrict__ Cf, __half* __restrict__ Ch)
{
    extern __shared__ __align__(128) char smc[];
    uint32_t sbase = (uint32_t)__cvta_generic_to_shared(smc);

    int tid = threadIdx.x;
    int tileM = blockIdx.y * BM, tileN = blockIdx.x * BN;
    const __half* A = (tileN >= nsplit) ? A1 : A0;
    int warp = tid >> 5, lane = tid & 31;
    int g8 = lane >> 2, t4 = lane & 3;
    int wm = (warp & 1) * 64;
    int wn = (warp >> 1) * 32;

    const __half* Ag = A + (size_t)tileM * K;
    const __half* Bg = B + (size_t)tileN * K;

    int q0 = tid, q1 = tid + 256;
    int r0s = q0 >> 2, c0s = (q0 & 3) * 8;
    int r1s = q1 >> 2, c1s = (q1 & 3) * 8;
    int szA0 = (tileM + r0s) < M ? 16 : 0;
    int szA1 = (tileM + r1s) < M ? 16 : 0;
    uint32_t dA0 = sbase + (uint32_t)(r0s * (BKH * 2) + c0s * 2);
    uint32_t dA1 = sbase + (uint32_t)(r1s * (BKH * 2) + c1s * 2);
    uint32_t dB0 = dA0 + TILE_B;
    uint32_t dB1 = dA1 + TILE_B;

    int mrowA = (lane & 7) + ((lane >> 3) & 1) * 8;
    int kcolA = (lane >> 4) * 8;
    uint32_t aOff = (uint32_t)(((wm + mrowA) * BKH + kcolA) * 2);
    int nrowB = ((lane >> 4) & 1) * 8 + (lane & 7);
    int kcolB = ((lane >> 3) & 1) * 8;
    uint32_t bOff = (uint32_t)(TILE_B + ((wn + nrowB) * BKH + kcolB) * 2);

    float acc[4][4][4];
#pragma unroll
    for (int i = 0; i < 4; i++)
#pragma unroll
        for (int j = 0; j < 4; j++)
#pragma unroll
            for (int r = 0; r < 4; r++) acc[i][j][r] = 0.f;

    int nt = K / BK;

#define HISSUE(tile, stage)                                                     \
    do {                                                                        \
        int kb_ = (tile) * BK;                                                  \
        uint32_t so_ = (uint32_t)((stage) * STAGE_B);                           \
        cp16(dA0 + so_, Ag + (size_t)r0s * K + kb_ + c0s, szA0);                \
        cp16(dA1 + so_, Ag + (size_t)r1s * K + kb_ + c1s, szA1);                \
        cp16(dB0 + so_, Bg + (size_t)r0s * K + kb_ + c0s, 16);                  \
        cp16(dB1 + so_, Bg + (size_t)r1s * K + kb_ + c1s, 16);                  \
    } while (0)

#pragma unroll
    for (int s = 0; s < STG - 1; s++) {
        if (s < nt) HISSUE(s, s);
        asm volatile("cp.async.commit_group;");
    }

    for (int t = 0; t < nt; t++) {
        asm volatile("cp.async.wait_group %0;" :: "n"(STG - 2));
        __syncthreads();

        int ntile = t + STG - 1;
        if (ntile < nt) HISSUE(ntile, ntile & (STG - 1));
        asm volatile("cp.async.commit_group;");

        uint32_t stg = sbase + (uint32_t)((t & (STG - 1)) * STAGE_B);

#pragma unroll
        for (int kk = 0; kk < 2; kk++) {
            uint32_t kby = (uint32_t)(kk * 16 * 2);
            uint32_t af[4][4], bfr[2][4];
#pragma unroll
            for (int i = 0; i < 4; i++)
                ldsm4(af[i], stg + aOff + (uint32_t)(i * 16 * BKH * 2) + kby);
#pragma unroll
            for (int jp = 0; jp < 2; jp++)
                ldsm4(bfr[jp], stg + bOff + (uint32_t)(jp * 16 * BKH * 2) + kby);
#pragma unroll
            for (int j = 0; j < 4; j++) {
                uint32_t b0 = bfr[j >> 1][(j & 1) * 2];
                uint32_t b1 = bfr[j >> 1][(j & 1) * 2 + 1];
#pragma unroll
                for (int i = 0; i < 4; i++) mma_f16(acc[i][j], af[i], b0, b1);
            }
        }
    }

    float cs[4][2], cb[4][2], cm[4][2];
    if (mode == 1) {
#pragma unroll
        for (int j = 0; j < 4; j++) {
            int c = tileN + wn + j * 8 + t4 * 2;
#pragma unroll
            for (int q = 0; q < 2; q++) {
                cs[j][q] = gv[c + q] * rsqrtf(vv[c + q] + 1e-5f);
                cb[j][q] = bv[c + q];
                cm[j][q] = mv[c + q];
            }
        }
    }

#pragma unroll
    for (int i = 0; i < 4; i++) {
#pragma unroll
        for (int h8 = 0; h8 < 2; h8++) {
            int r = tileM + wm + i * 16 + g8 + h8 * 8;
            if (r >= M) continue;
#pragma unroll
            for (int j = 0; j < 4; j++) {
                int c = tileN + wn + j * 8 + t4 * 2;
                float v0 = acc[i][j][h8 * 2 + 0];
                float v1 = acc[i][j][h8 * 2 + 1];
                if (mode == 1) {
                    v0 = fmaxf((v0 - cm[j][0]) * cs[j][0] + cb[j][0], 0.f);
                    v1 = fmaxf((v1 - cm[j][1]) * cs[j][1] + cb[j][1], 0.f);
                    __half2 hv;
                    hv.x = __float2half(v0);
                    hv.y = __float2half(v1);
                    *(__half2*)(Ch + (size_t)r * Ncols + c) = hv;
                } else if (mode == 2) {
                    v0 = v0 > 0.f ? v0 : 0.01f * v0;
                    v1 = v1 > 0.f ? v1 : 0.01f * v1;
                    __half2 hv;
                    hv.x = __float2half(v0);
                    hv.y = __float2half(v1);
                    *(__half2*)(Ch + (size_t)r * Ncols + c) = hv;
                } else if (mode == 3) {
                    __half2 hv;
                    hv.x = __float2half(v0);
                    hv.y = __float2half(v1);
                    *(__half2*)(Ch + (size_t)r * Ncols + c) = hv;
                } else {
                    *(float2*)(Cf + (size_t)r * Ncols + c) = make_float2(v0, v1);
                }
            }
        }
    }
}

// ---------------- host orchestration (single stream) ----------------
extern "C" void kernel_launch(void* const* d_in, const int* in_sizes, int n_in,
                              void* d_out, int out_size) {
    const float* x  = (const float*)d_in[0];
    const int*   ei = (const int*)d_in[1];
    const float* ea = (const float*)d_in[2];
    int base = 3;
    if (n_in > 19) base = 3 + (n_in - 19);
    const float* l0_src  = (const float*)d_in[base + 0];
    const float* l0_dst  = (const float*)d_in[base + 1];
    const float* l0_edge = (const float*)d_in[base + 2];
    const float* l0_w1   = (const float*)d_in[base + 3];
    const float* l0_g    = (const float*)d_in[base + 4];
    const float* l0_b    = (const float*)d_in[base + 5];
    const float* l0_m    = (const float*)d_in[base + 6];
    const float* l0_v    = (const float*)d_in[base + 7];
    const float* l0_w2   = (const float*)d_in[base + 8];
    const float* l1_edge = (const float*)d_in[base + 9];
    const float* l1_w1   = (const float*)d_in[base + 10];
    const float* l1_g    = (const float*)d_in[base + 11];
    const float* l1_b    = (const float*)d_in[base + 12];
    const float* l1_m    = (const float*)d_in[base + 13];
    const float* l1_v    = (const float*)d_in[base + 14];
    const float* l1_w2   = (const float*)d_in[base + 15];
    float* out = (float*)d_out;

    __half *sfdf, *x1h, *xh, *ob, *hb, *wcat, *w01, *w02c, *w11, *w12c;
    int *rowptr, *cursor, *eidx;
    cudaGetSymbolAddress((void**)&sfdf, g_sfdf);
    cudaGetSymbolAddress((void**)&x1h, g_x1);
    cudaGetSymbolAddress((void**)&xh, g_xh);
    cudaGetSymbolAddress((void**)&ob, g_ob);
    cudaGetSymbolAddress((void**)&hb, g_hb);
    cudaGetSymbolAddress((void**)&wcat, g_wcat);
    cudaGetSymbolAddress((void**)&w01, g_w01);
    cudaGetSymbolAddress((void**)&w02c, g_w02c);
    cudaGetSymbolAddress((void**)&w11, g_w11);
    cudaGetSymbolAddress((void**)&w12c, g_w12c);
    cudaGetSymbolAddress((void**)&rowptr, g_rowptr);
    cudaGetSymbolAddress((void**)&cursor, g_cursor);
    cudaGetSymbolAddress((void**)&eidx, g_eidx);

    cudaFuncSetAttribute(k_hgemm, cudaFuncAttributeMaxDynamicSharedMemorySize, DSMEM);

    const int* dstBoth = ei + ETOT;
    const int BIG = 1 << 30;

    // ---- fp16 operand conversion ----
    k_half<<<(NN * FINC + 255) / 256, 256>>>(x, xh, NN * FINC);
    k_half_cat<<<(2 * HC * FINC + 255) / 256, 256>>>(l0_src, wcat, 0);
    k_half_cat<<<(2 * HC * FINC + 255) / 256, 256>>>(l0_dst, wcat, 512);
    k_half<<<(2 * H2C * HC + 255) / 256, 256>>>(l0_w1, w01, 2 * H2C * HC);
    k_half_w2cat<<<(2 * HC * H2C + 255) / 256, 256>>>(l0_w2, w02c);
    k_half<<<(2 * H2C * HC + 255) / 256, 256>>>(l1_w1, w11, 2 * H2C * HC);
    k_half_w2cat<<<(2 * HC * H2C + 255) / 256, 256>>>(l1_w2, w12c);

    // ---- CSR build ----
    k_zero_int<<<(2 * NN + 255) / 256, 256>>>(cursor, 2 * NN);
    k_count_deg2<<<(2 * LPART + 255) / 256, 256>>>(dstBoth, cursor);
    k_scan2<<<2, 1024>>>(cursor, rowptr);
    k_copy_rp2<<<(2 * NN + 255) / 256, 256>>>(rowptr, cursor);
    k_scatter2<<<(2 * LPART + 255) / 256, 256>>>(dstBoth, cursor, eidx);
    k_sort_buckets2<<<(2 * NN + 127) / 128, 128>>>(rowptr, eidx);

    dim3 blk(256);
    int gy = (NN + BM - 1) / BM;
    dim3 gproj(2048 / BN, gy), g512(HC / BN, gy), g2048(2048 / BN, gy);

    // ---- layer 0 ----
    // projections: sfdf[NN,2048] fp16
    k_hgemm<<<gproj, blk, DSMEM>>>(xh, xh, BIG, wcat, NN, FINC, 2048, 3,
                                   nullptr, nullptr, nullptr, nullptr, nullptr, sfdf);
    // both aggs in one launch
    k_agg2<<<(2 * NN) / 4, 128>>>(sfdf, 1024, 2048, sfdf + 512, 1024, 2048,
                                  l0_edge, ea, ei, rowptr, eidx, ob);
    // W1 dual-A: hb[NN,2048]
    k_hgemm<<<g2048, blk, DSMEM>>>(ob, ob + (size_t)NN * HC, 1024, w01,
                                   NN, HC, 2048, 1, l0_g, l0_b, l0_m, l0_v,
                                   nullptr, hb);
    // W2 merged K=2048, fused leaky -> x1 fp16
    k_hgemm<<<g512, blk, DSMEM>>>(hb, hb, BIG, w02c, NN, 2048, HC, 2,
                                  nullptr, nullptr, nullptr, nullptr, nullptr, x1h);

    // ---- layer 1 ----
    k_agg2<<<(2 * NN) / 4, 128>>>(x1h, 0, HC, x1h, 0, HC,
                                  l1_edge, ea, ei, rowptr, eidx, ob);
    k_hgemm<<<g2048, blk, DSMEM>>>(ob, ob + (size_t)NN * HC, 1024, w11,
                                   NN, HC, 2048, 1, l1_g, l1_b, l1_m, l1_v,
                                   nullptr, hb);
    k_hgemm<<<g512, blk, DSMEM>>>(hb, hb, BIG, w12c, NN, 2048, HC, 0,
                                  nullptr, nullptr, nullptr, nullptr, out, nullptr);
}

// round 12
// speedup vs baseline: 1.7323x; 1.0935x over previous
#include <cuda_runtime.h>
#include <cuda_fp16.h>
#include <math.h>
#include <stdint.h>

#define NN 20000
#define ETOT 150000
#define LPART 75000
#define FINC 256
#define HC 512
#define H2C 1024

// ---------------- static device scratch ----------------
__device__ __half g_sfdf[NN * 2048];   // layer0 merged projections (fp16)
__device__ __half g_x1[NN * HC];       // leaky output (fp16)
__device__ __half g_xh[NN * FINC];
__device__ __half g_ob[2 * NN * HC];   // per-link agg outputs
__device__ __half g_hb[NN * 2048];     // merged W1 outputs [NN][l*1024+..]
__device__ __half g_wcat[2048 * FINC];
__device__ __half g_w01[2 * H2C * HC];
__device__ __half g_w02c[HC * 2048];
__device__ __half g_w11[2 * H2C * HC];
__device__ __half g_w12c[HC * 2048];
__device__ int g_rowptr[2][NN + 1];
__device__ int g_cursor[2][NN];
__device__ int g_eidx[2][LPART];

// ---------------- CSR build (both partitions fused per launch) ----------------
__global__ void k_zero_int(int* p, int n) {
    int i = blockIdx.x * blockDim.x + threadIdx.x;
    if (i < n) p[i] = 0;
}

__global__ void k_count_deg2(const int* __restrict__ dstBoth, int* __restrict__ deg) {
    int i = blockIdx.x * blockDim.x + threadIdx.x;
    if (i < 2 * LPART) {
        int p = i / LPART;
        atomicAdd(&deg[p * NN + dstBoth[i]], 1);
    }
}

__global__ void k_scan2(const int* __restrict__ deg, int* __restrict__ rowptr) {
    __shared__ int sbuf[1024];
    __shared__ int carry;
    int p = blockIdx.x;
    const int* d = deg + p * NN;
    int* rp = rowptr + p * (NN + 1);
    int t = threadIdx.x;
    if (t == 0) { carry = 0; rp[0] = 0; }
    __syncthreads();
    for (int base = 0; base < NN; base += 1024) {
        int v = (base + t < NN) ? d[base + t] : 0;
        sbuf[t] = v;
        __syncthreads();
        for (int off = 1; off < 1024; off <<= 1) {
            int nv = (t >= off) ? sbuf[t - off] : 0;
            __syncthreads();
            sbuf[t] += nv;
            __syncthreads();
        }
        if (base + t < NN) rp[base + t + 1] = carry + sbuf[t];
        __syncthreads();
        if (t == 0) carry += sbuf[1023];
        __syncthreads();
    }
}

__global__ void k_copy_rp2(const int* __restrict__ rowptr, int* __restrict__ cursor) {
    int i = blockIdx.x * blockDim.x + threadIdx.x;
    if (i < 2 * NN) {
        int p = i / NN, r = i % NN;
        cursor[i] = rowptr[p * (NN + 1) + r];
    }
}

__global__ void k_scatter2(const int* __restrict__ dstBoth, int* __restrict__ cursor,
                           int* __restrict__ eidx) {
    int i = blockIdx.x * blockDim.x + threadIdx.x;
    if (i < 2 * LPART) {
        int p = i / LPART;
        int pos = atomicAdd(&cursor[p * NN + dstBoth[i]], 1);
        eidx[p * LPART + pos] = i - p * LPART;
    }
}

__global__ void k_sort_buckets2(const int* __restrict__ rowptr, int* __restrict__ eidx) {
    int i = blockIdx.x * blockDim.x + threadIdx.x;
    if (i >= 2 * NN) return;
    int p = i / NN, node = i % NN;
    const int* rp = rowptr + p * (NN + 1);
    int* ex = eidx + p * LPART;
    int a = rp[node], b = rp[node + 1];
    for (int q = a + 1; q < b; q++) {
        int key = ex[q];
        int j = q - 1;
        while (j >= a && ex[j] > key) { ex[j + 1] = ex[j]; j--; }
        ex[j + 1] = key;
    }
}

__global__ void k_half(const float* __restrict__ s, __half* __restrict__ h, int n) {
    int i = blockIdx.x * blockDim.x + threadIdx.x;
    if (i < n) h[i] = __float2half(s[i]);
}

__global__ void k_half_cat(const float* __restrict__ s, __half* __restrict__ wcat, int off) {
    int i = blockIdx.x * blockDim.x + threadIdx.x;
    if (i >= 2 * HC * FINC) return;
    int l = i >> 17;
    int rem = i & 131071;
    int rr = rem >> 8;
    int c = rem & 255;
    wcat[((l * 1024 + off + rr) << 8) + c] = __float2half(s[i]);
}

// W2 K-concat: in [2][512][1024] -> out[n][l*1024+kk]
__global__ void k_half_w2cat(const float* __restrict__ s, __half* __restrict__ w) {
    int i = blockIdx.x * blockDim.x + threadIdx.x;
    if (i >= 2 * HC * H2C) return;
    int l = i >> 19;
    int rem = i & 524287;
    int n = rem >> 10;
    int kk = rem & 1023;
    w[n * 2048 + (l << 10) + kk] = __float2half(s[i]);
}

// ---------------- merged per-layer edge softmax aggregation (all fp16) -----------
__global__ __launch_bounds__(128) void k_agg2(
    const __half* __restrict__ sf_base, int sf_loff, int sstr,
    const __half* __restrict__ df_base, int df_loff, int dstr,
    const float* __restrict__ WeBoth,
    const float* __restrict__ ea,
    const int* __restrict__ srcBoth,
    const int* __restrict__ rowptr,
    const int* __restrict__ eidx,
    __half* __restrict__ oh)
{
    __shared__ float wsh[HC];
    int t = threadIdx.x;
    int pblk = (blockIdx.x * 4) / NN;
    for (int i = t; i < HC; i += 128) wsh[i] = WeBoth[pblk * HC + i];
    __syncthreads();

    int warp = t >> 5, lane = t & 31;
    int gw = blockIdx.x * 4 + warp;
    if (gw >= 2 * NN) return;
    int p = gw >= NN;
    int node = gw - p * NN;

    const __half2* sfeat = (const __half2*)(sf_base + (size_t)p * sf_loff);
    const __half2* dfeat = (const __half2*)(df_base + (size_t)p * df_loff);
    int s2 = sstr >> 1, d2 = dstr >> 1;
    const float* eap = ea + (size_t)p * LPART;
    const int* srcp = srcBoth + (size_t)p * LPART;
    const int* rp = rowptr + p * (NN + 1);
    const int* ex = eidx + (size_t)p * LPART;

    float wv[16];
#pragma unroll
    for (int jj = 0; jj < 8; jj++) {
        int q = lane + 32 * jj;
        wv[2 * jj] = wsh[2 * q];
        wv[2 * jj + 1] = wsh[2 * q + 1];
    }

    float m[16], s[16], tt[16];
#pragma unroll
    for (int j = 0; j < 16; j++) { m[j] = -INFINITY; s[j] = 0.f; tt[j] = 0.f; }

    int e0 = rp[node], e1 = rp[node + 1];
    for (int e = e0; e < e1; e++) {
        int eid = ex[e];
        int sidx = srcp[eid];
        float a = eap[eid];
        const __half2* row = sfeat + (size_t)sidx * s2;
#pragma unroll
        for (int jj = 0; jj < 8; jj++) {
            float2 v = __half22float2(row[lane + 32 * jj]);
#pragma unroll
            for (int h = 0; h < 2; h++) {
                int j = 2 * jj + h;
                float msg = fmaxf((h ? v.y : v.x) + a * wv[j], 0.f) + 1e-7f;
                float mn = fmaxf(m[j], msg);
                float scale = __expf(m[j] - mn);
                float pr = __expf(msg - mn);
                s[j] = s[j] * scale + pr;
                tt[j] = tt[j] * scale + msg * pr;
                m[j] = mn;
            }
        }
    }
    const __half2* drow = dfeat + (size_t)node * d2;
    __half2* hrow = (__half2*)(oh + ((size_t)p * NN + node) * HC);
#pragma unroll
    for (int jj = 0; jj < 8; jj++) {
        float2 dv = __half22float2(drow[lane + 32 * jj]);
        float o0 = tt[2 * jj] / (s[2 * jj] + 1e-16f) + dv.x;
        float o1 = tt[2 * jj + 1] / (s[2 * jj + 1] + 1e-16f) + dv.y;
        hrow[lane + 32 * jj] = __floats2half2_rn(o0, o1);
    }
}

// ---------------- fp16 GEMM: 128x128x64, cp.async 3-stage, ldmatrix --------------
// dual-A: blocks with tileN >= nsplit read A1.
// mode 0: fp32 store. mode 1: BN+ReLU -> fp16. mode 2: leaky -> fp16. mode 3: fp16.
#define BM 128
#define BN 128
#define BK 64
#define BKH 72
#define STG 3
#define TILE_BYTES (BM * BKH * 2)          // 18432
#define STAGE_B (2 * TILE_BYTES)           // 36864
#define DSMEM (STG * STAGE_B)              // 110592 (2 CTAs/SM: 216KB <= 228KB)

__device__ __forceinline__ void mma_f16(float* c, const uint32_t* a, uint32_t b0, uint32_t b1) {
    asm volatile(
        "mma.sync.aligned.m16n8k16.row.col.f32.f16.f16.f32 "
        "{%0,%1,%2,%3}, {%4,%5,%6,%7}, {%8,%9}, {%0,%1,%2,%3};"
        : "+f"(c[0]), "+f"(c[1]), "+f"(c[2]), "+f"(c[3])
        : "r"(a[0]), "r"(a[1]), "r"(a[2]), "r"(a[3]), "r"(b0), "r"(b1));
}

__device__ __forceinline__ void ldsm4(uint32_t* r, uint32_t addr) {
    asm volatile("ldmatrix.sync.aligned.m8n8.x4.shared.b16 {%0,%1,%2,%3}, [%4];"
                 : "=r"(r[0]), "=r"(r[1]), "=r"(r[2]), "=r"(r[3]) : "r"(addr));
}

__device__ __forceinline__ void cp16(uint32_t saddr, const void* gaddr, int srcbytes) {
    asm volatile("cp.async.cg.shared.global [%0], [%1], 16, %2;"
                 :: "r"(saddr), "l"(gaddr), "r"(srcbytes));
}

__global__ __launch_bounds__(256, 2) void k_hgemm(
    const __half* __restrict__ A0, const __half* __restrict__ A1, int nsplit,
    const __half* __restrict__ B,
    int M, int K, int Ncols, int mode,
    const float* __restrict__ gv, const float* __restrict__ bv,
    const float* __restrict__ mv, const float* __restrict__ vv,
    float* __restrict__ Cf, __half* __restrict__ Ch)
{
    extern __shared__ __align__(128) char smc[];
    uint32_t sbase = (uint32_t)__cvta_generic_to_shared(smc);

    int tid = threadIdx.x;
    int tileM = blockIdx.y * BM, tileN = blockIdx.x * BN;
    const __half* A = (tileN >= nsplit) ? A1 : A0;
    int warp = tid >> 5, lane = tid & 31;
    int g8 = lane >> 2, t4 = lane & 3;
    int wm = (warp & 1) * 64;
    int wn = (warp >> 1) * 32;

    const __half* Ag = A + (size_t)tileM * K;
    const __half* Bg = B + (size_t)tileN * K;

    // staging: 1024 chunks (16B) per matrix, 4 per thread each
    int rA[4], cA[4], szA[4];
    uint32_t dA[4], dB[4];
#pragma unroll
    for (int i = 0; i < 4; i++) {
        int q = tid + i * 256;
        rA[i] = q >> 3;
        cA[i] = (q & 7) * 8;
        szA[i] = (tileM + rA[i]) < M ? 16 : 0;
        dA[i] = sbase + (uint32_t)((rA[i] * BKH + cA[i]) * 2);
        dB[i] = dA[i] + TILE_BYTES;
    }

    int mrowA = (lane & 7) + ((lane >> 3) & 1) * 8;
    int kcolA = (lane >> 4) * 8;
    uint32_t aOff = (uint32_t)(((wm + mrowA) * BKH + kcolA) * 2);
    int nrowB = ((lane >> 4) & 1) * 8 + (lane & 7);
    int kcolB = ((lane >> 3) & 1) * 8;
    uint32_t bOff = (uint32_t)(TILE_BYTES + ((wn + nrowB) * BKH + kcolB) * 2);

    float acc[4][4][4];
#pragma unroll
    for (int i = 0; i < 4; i++)
#pragma unroll
        for (int j = 0; j < 4; j++)
#pragma unroll
            for (int r = 0; r < 4; r++) acc[i][j][r] = 0.f;

    int nt = K / BK;

#define HISSUE(tile, stage)                                                     \
    do {                                                                        \
        int kb_ = (tile) * BK;                                                  \
        uint32_t so_ = (uint32_t)((stage) * STAGE_B);                           \
        _Pragma("unroll")                                                       \
        for (int ii = 0; ii < 4; ii++) {                                        \
            cp16(dA[ii] + so_, Ag + (size_t)rA[ii] * K + kb_ + cA[ii], szA[ii]);\
            cp16(dB[ii] + so_, Bg + (size_t)rA[ii] * K + kb_ + cA[ii], 16);     \
        }                                                                       \
    } while (0)

#pragma unroll
    for (int s = 0; s < STG - 1; s++) {
        if (s < nt) HISSUE(s, s);
        asm volatile("cp.async.commit_group;");
    }

    int stage = 0;
    for (int t = 0; t < nt; t++) {
        asm volatile("cp.async.wait_group %0;" :: "n"(STG - 2));
        __syncthreads();

        int ntile = t + STG - 1;
        int nstage = stage + STG - 1;
        if (nstage >= STG) nstage -= STG;
        if (ntile < nt) HISSUE(ntile, nstage);
        asm volatile("cp.async.commit_group;");

        uint32_t stg = sbase + (uint32_t)(stage * STAGE_B);

#pragma unroll
        for (int kk = 0; kk < 4; kk++) {
            uint32_t kby = (uint32_t)(kk * 16 * 2);
            uint32_t af[4][4], bfr[2][4];
#pragma unroll
            for (int i = 0; i < 4; i++)
                ldsm4(af[i], stg + aOff + (uint32_t)(i * 16 * BKH * 2) + kby);
#pragma unroll
            for (int jp = 0; jp < 2; jp++)
                ldsm4(bfr[jp], stg + bOff + (uint32_t)(jp * 16 * BKH * 2) + kby);
#pragma unroll
            for (int j = 0; j < 4; j++) {
                uint32_t b0 = bfr[j >> 1][(j & 1) * 2];
                uint32_t b1 = bfr[j >> 1][(j & 1) * 2 + 1];
#pragma unroll
                for (int i = 0; i < 4; i++) mma_f16(acc[i][j], af[i], b0, b1);
            }
        }
        if (++stage == STG) stage = 0;
    }

    float cs[4][2], cb[4][2], cm[4][2];
    if (mode == 1) {
#pragma unroll
        for (int j = 0; j < 4; j++) {
            int c = tileN + wn + j * 8 + t4 * 2;
#pragma unroll
            for (int q = 0; q < 2; q++) {
                cs[j][q] = gv[c + q] * rsqrtf(vv[c + q] + 1e-5f);
                cb[j][q] = bv[c + q];
                cm[j][q] = mv[c + q];
            }
        }
    }

#pragma unroll
    for (int i = 0; i < 4; i++) {
#pragma unroll
        for (int h8 = 0; h8 < 2; h8++) {
            int r = tileM + wm + i * 16 + g8 + h8 * 8;
            if (r >= M) continue;
#pragma unroll
            for (int j = 0; j < 4; j++) {
                int c = tileN + wn + j * 8 + t4 * 2;
                float v0 = acc[i][j][h8 * 2 + 0];
                float v1 = acc[i][j][h8 * 2 + 1];
                if (mode == 1) {
                    v0 = fmaxf((v0 - cm[j][0]) * cs[j][0] + cb[j][0], 0.f);
                    v1 = fmaxf((v1 - cm[j][1]) * cs[j][1] + cb[j][1], 0.f);
                    __half2 hv;
                    hv.x = __float2half(v0);
                    hv.y = __float2half(v1);
                    *(__half2*)(Ch + (size_t)r * Ncols + c) = hv;
                } else if (mode == 2) {
                    v0 = v0 > 0.f ? v0 : 0.01f * v0;
                    v1 = v1 > 0.f ? v1 : 0.01f * v1;
                    __half2 hv;
                    hv.x = __float2half(v0);
                    hv.y = __float2half(v1);
                    *(__half2*)(Ch + (size_t)r * Ncols + c) = hv;
                } else if (mode == 3) {
                    __half2 hv;
                    hv.x = __float2half(v0);
                    hv.y = __float2half(v1);
                    *(__half2*)(Ch + (size_t)r * Ncols + c) = hv;
                } else {
                    *(float2*)(Cf + (size_t)r * Ncols + c) = make_float2(v0, v1);
                }
            }
        }
    }
}

// ---------------- host orchestration (single stream) ----------------
extern "C" void kernel_launch(void* const* d_in, const int* in_sizes, int n_in,
                              void* d_out, int out_size) {
    const float* x  = (const float*)d_in[0];
    const int*   ei = (const int*)d_in[1];
    const float* ea = (const float*)d_in[2];
    int base = 3;
    if (n_in > 19) base = 3 + (n_in - 19);
    const float* l0_src  = (const float*)d_in[base + 0];
    const float* l0_dst  = (const float*)d_in[base + 1];
    const float* l0_edge = (const float*)d_in[base + 2];
    const float* l0_w1   = (const float*)d_in[base + 3];
    const float* l0_g    = (const float*)d_in[base + 4];
    const float* l0_b    = (const float*)d_in[base + 5];
    const float* l0_m    = (const float*)d_in[base + 6];
    const float* l0_v    = (const float*)d_in[base + 7];
    const float* l0_w2   = (const float*)d_in[base + 8];
    const float* l1_edge = (const float*)d_in[base + 9];
    const float* l1_w1   = (const float*)d_in[base + 10];
    const float* l1_g    = (const float*)d_in[base + 11];
    const float* l1_b    = (const float*)d_in[base + 12];
    const float* l1_m    = (const float*)d_in[base + 13];
    const float* l1_v    = (const float*)d_in[base + 14];
    const float* l1_w2   = (const float*)d_in[base + 15];
    float* out = (float*)d_out;

    __half *sfdf, *x1h, *xh, *ob, *hb, *wcat, *w01, *w02c, *w11, *w12c;
    int *rowptr, *cursor, *eidx;
    cudaGetSymbolAddress((void**)&sfdf, g_sfdf);
    cudaGetSymbolAddress((void**)&x1h, g_x1);
    cudaGetSymbolAddress((void**)&xh, g_xh);
    cudaGetSymbolAddress((void**)&ob, g_ob);
    cudaGetSymbolAddress((void**)&hb, g_hb);
    cudaGetSymbolAddress((void**)&wcat, g_wcat);
    cudaGetSymbolAddress((void**)&w01, g_w01);
    cudaGetSymbolAddress((void**)&w02c, g_w02c);
    cudaGetSymbolAddress((void**)&w11, g_w11);
    cudaGetSymbolAddress((void**)&w12c, g_w12c);
    cudaGetSymbolAddress((void**)&rowptr, g_rowptr);
    cudaGetSymbolAddress((void**)&cursor, g_cursor);
    cudaGetSymbolAddress((void**)&eidx, g_eidx);

    cudaFuncSetAttribute(k_hgemm, cudaFuncAttributeMaxDynamicSharedMemorySize, DSMEM);

    const int* dstBoth = ei + ETOT;
    const int BIG = 1 << 30;

    // ---- fp16 operand conversion ----
    k_half<<<(NN * FINC + 255) / 256, 256>>>(x, xh, NN * FINC);
    k_half_cat<<<(2 * HC * FINC + 255) / 256, 256>>>(l0_src, wcat, 0);
    k_half_cat<<<(2 * HC * FINC + 255) / 256, 256>>>(l0_dst, wcat, 512);
    k_half<<<(2 * H2C * HC + 255) / 256, 256>>>(l0_w1, w01, 2 * H2C * HC);
    k_half_w2cat<<<(2 * HC * H2C + 255) / 256, 256>>>(l0_w2, w02c);
    k_half<<<(2 * H2C * HC + 255) / 256, 256>>>(l1_w1, w11, 2 * H2C * HC);
    k_half_w2cat<<<(2 * HC * H2C + 255) / 256, 256>>>(l1_w2, w12c);

    // ---- CSR build ----
    k_zero_int<<<(2 * NN + 255) / 256, 256>>>(cursor, 2 * NN);
    k_count_deg2<<<(2 * LPART + 255) / 256, 256>>>(dstBoth, cursor);
    k_scan2<<<2, 1024>>>(cursor, rowptr);
    k_copy_rp2<<<(2 * NN + 255) / 256, 256>>>(rowptr, cursor);
    k_scatter2<<<(2 * LPART + 255) / 256, 256>>>(dstBoth, cursor, eidx);
    k_sort_buckets2<<<(2 * NN + 127) / 128, 128>>>(rowptr, eidx);

    dim3 blk(256);
    int gy = (NN + BM - 1) / BM;
    dim3 gproj(2048 / BN, gy), g512(HC / BN, gy), g2048(2048 / BN, gy);

    // ---- layer 0 ----
    k_hgemm<<<gproj, blk, DSMEM>>>(xh, xh, BIG, wcat, NN, FINC, 2048, 3,
                                   nullptr, nullptr, nullptr, nullptr, nullptr, sfdf);
    k_agg2<<<(2 * NN) / 4, 128>>>(sfdf, 1024, 2048, sfdf + 512, 1024, 2048,
                                  l0_edge, ea, ei, rowptr, eidx, ob);
    k_hgemm<<<g2048, blk, DSMEM>>>(ob, ob + (size_t)NN * HC, 1024, w01,
                                   NN, HC, 2048, 1, l0_g, l0_b, l0_m, l0_v,
                                   nullptr, hb);
    k_hgemm<<<g512, blk, DSMEM>>>(hb, hb, BIG, w02c, NN, 2048, HC, 2,
                                  nullptr, nullptr, nullptr, nullptr, nullptr, x1h);

    // ---- layer 1 ----
    k_agg2<<<(2 * NN) / 4, 128>>>(x1h, 0, HC, x1h, 0, HC,
                                  l1_edge, ea, ei, rowptr, eidx, ob);
    k_hgemm<<<g2048, blk, DSMEM>>>(ob, ob + (size_t)NN * HC, 1024, w11,
                                   NN, HC, 2048, 1, l1_g, l1_b, l1_m, l1_v,
                                   nullptr, hb);
    k_hgemm<<<g512, blk, DSMEM>>>(hb, hb, BIG, w12c, NN, 2048, HC, 0,
                                  nullptr, nullptr, nullptr, nullptr, out, nullptr);
}

// round 13
// speedup vs baseline: 1.7445x; 1.0070x over previous
#include <cuda_runtime.h>
#include <cuda_fp16.h>
#include <math.h>
#include <stdint.h>

#define NN 20000
#define ETOT 150000
#define LPART 75000
#define FINC 256
#define HC 512
#define H2C 1024

// ---------------- static device scratch ----------------
__device__ __half g_sfdf[NN * 2048];   // layer0 merged projections (fp16)
__device__ __half g_x1[NN * HC];       // leaky output (fp16)
__device__ __half g_xh[NN * FINC];
__device__ __half g_ob[2 * NN * HC];   // per-link agg outputs
__device__ __half g_hb[NN * 2048];     // merged W1 outputs
__device__ __half g_wcat[2048 * FINC];
__device__ __half g_w01[2 * H2C * HC];
__device__ __half g_w02c[HC * 2048];
__device__ __half g_w11[2 * H2C * HC];
__device__ __half g_w12c[HC * 2048];
__device__ int g_rowptr[2][NN + 1];
__device__ int g_cursor[2][NN];
__device__ int g_eidx[2][LPART];

// ---------------- CSR build (both partitions fused per launch) ----------------
__global__ void k_zero_int(int* p, int n) {
    int i = blockIdx.x * blockDim.x + threadIdx.x;
    if (i < n) p[i] = 0;
}

__global__ void k_count_deg2(const int* __restrict__ dstBoth, int* __restrict__ deg) {
    int i = blockIdx.x * blockDim.x + threadIdx.x;
    if (i < 2 * LPART) {
        int p = i / LPART;
        atomicAdd(&deg[p * NN + dstBoth[i]], 1);
    }
}

__global__ void k_scan2(const int* __restrict__ deg, int* __restrict__ rowptr) {
    __shared__ int sbuf[1024];
    __shared__ int carry;
    int p = blockIdx.x;
    const int* d = deg + p * NN;
    int* rp = rowptr + p * (NN + 1);
    int t = threadIdx.x;
    if (t == 0) { carry = 0; rp[0] = 0; }
    __syncthreads();
    for (int base = 0; base < NN; base += 1024) {
        int v = (base + t < NN) ? d[base + t] : 0;
        sbuf[t] = v;
        __syncthreads();
        for (int off = 1; off < 1024; off <<= 1) {
            int nv = (t >= off) ? sbuf[t - off] : 0;
            __syncthreads();
            sbuf[t] += nv;
            __syncthreads();
        }
        if (base + t < NN) rp[base + t + 1] = carry + sbuf[t];
        __syncthreads();
        if (t == 0) carry += sbuf[1023];
        __syncthreads();
    }
}

__global__ void k_copy_rp2(const int* __restrict__ rowptr, int* __restrict__ cursor) {
    int i = blockIdx.x * blockDim.x + threadIdx.x;
    if (i < 2 * NN) {
        int p = i / NN, r = i % NN;
        cursor[i] = rowptr[p * (NN + 1) + r];
    }
}

__global__ void k_scatter2(const int* __restrict__ dstBoth, int* __restrict__ cursor,
                           int* __restrict__ eidx) {
    int i = blockIdx.x * blockDim.x + threadIdx.x;
    if (i < 2 * LPART) {
        int p = i / LPART;
        int pos = atomicAdd(&cursor[p * NN + dstBoth[i]], 1);
        eidx[p * LPART + pos] = i - p * LPART;
    }
}

__global__ void k_sort_buckets2(const int* __restrict__ rowptr, int* __restrict__ eidx) {
    int i = blockIdx.x * blockDim.x + threadIdx.x;
    if (i >= 2 * NN) return;
    int p = i / NN, node = i % NN;
    const int* rp = rowptr + p * (NN + 1);
    int* ex = eidx + p * LPART;
    int a = rp[node], b = rp[node + 1];
    for (int q = a + 1; q < b; q++) {
        int key = ex[q];
        int j = q - 1;
        while (j >= a && ex[j] > key) { ex[j + 1] = ex[j]; j--; }
        ex[j + 1] = key;
    }
}

// ---------------- fused conversions ----------------
__global__ void k_half(const float* __restrict__ s, __half* __restrict__ h, int n) {
    int i = blockIdx.x * blockDim.x + threadIdx.x;
    if (i < n) h[i] = __float2half(s[i]);
}

// src (off 0) and dst (off 512) projection weights -> wcat in ONE launch
__global__ void k_half_cat2(const float* __restrict__ ssrc, const float* __restrict__ sdst,
                            __half* __restrict__ wcat) {
    int i = blockIdx.x * blockDim.x + threadIdx.x;
    int NEL = 2 * HC * FINC;
    if (i >= 2 * NEL) return;
    int which = i >= NEL;
    int ii = i - which * NEL;
    const float* s = which ? sdst : ssrc;
    int off = which ? 512 : 0;
    int l = ii >> 17;
    int rem = ii & 131071;
    int rr = rem >> 8;
    int c = rem & 255;
    wcat[((l * 1024 + off + rr) << 8) + c] = __float2half(s[ii]);
}

// two plain conversions (w1 layer0 + layer1) in one launch
__global__ void k_half2x(const float* __restrict__ s0, __half* __restrict__ h0,
                         const float* __restrict__ s1, __half* __restrict__ h1, int n) {
    int i = blockIdx.x * blockDim.x + threadIdx.x;
    if (i < n) h0[i] = __float2half(s0[i]);
    else if (i < 2 * n) h1[i - n] = __float2half(s1[i - n]);
}

// W2 K-concat for both layers in one launch: in [2][512][1024] -> out[n][l*1024+kk]
__global__ void k_half_w2cat2(const float* __restrict__ s0, __half* __restrict__ w0,
                              const float* __restrict__ s1, __half* __restrict__ w1) {
    int i = blockIdx.x * blockDim.x + threadIdx.x;
    int NEL = 2 * HC * H2C;
    if (i >= 2 * NEL) return;
    int which = i >= NEL;
    int ii = i - which * NEL;
    const float* s = which ? s1 : s0;
    __half* w = which ? w1 : w0;
    int l = ii >> 19;
    int rem = ii & 524287;
    int n = rem >> 10;
    int kk = rem & 1023;
    w[n * 2048 + (l << 10) + kk] = __float2half(s[ii]);
}

// ---------------- merged per-layer edge softmax aggregation (int4 loads) ---------
// lane owns halfs [8*lane .. 8*lane+7] and [8*(lane+32) .. 8*(lane+32)+7]
__global__ __launch_bounds__(128) void k_agg2(
    const __half* __restrict__ sf_base, int sf_loff, int sstr,
    const __half* __restrict__ df_base, int df_loff, int dstr,
    const float* __restrict__ WeBoth,
    const float* __restrict__ ea,
    const int* __restrict__ srcBoth,
    const int* __restrict__ rowptr,
    const int* __restrict__ eidx,
    __half* __restrict__ oh)
{
    __shared__ float wsh[HC];
    int t = threadIdx.x;
    int pblk = (blockIdx.x * 4) / NN;
    for (int i = t; i < HC; i += 128) wsh[i] = WeBoth[pblk * HC + i];
    __syncthreads();

    int warp = t >> 5, lane = t & 31;
    int gw = blockIdx.x * 4 + warp;
    if (gw >= 2 * NN) return;
    int p = gw >= NN;
    int node = gw - p * NN;

    const int4* sfeat = (const int4*)(sf_base + (size_t)p * sf_loff);
    const int4* dfeat = (const int4*)(df_base + (size_t)p * df_loff);
    int s4 = sstr >> 3, d4 = dstr >> 3;
    const float* eap = ea + (size_t)p * LPART;
    const int* srcp = srcBoth + (size_t)p * LPART;
    const int* rp = rowptr + p * (NN + 1);
    const int* ex = eidx + (size_t)p * LPART;

    float wv[16];
#pragma unroll
    for (int k = 0; k < 8; k++) {
        wv[k] = wsh[8 * lane + k];
        wv[8 + k] = wsh[8 * (lane + 32) + k];
    }

    float m[16], s[16], tt[16];
#pragma unroll
    for (int j = 0; j < 16; j++) { m[j] = -INFINITY; s[j] = 0.f; tt[j] = 0.f; }

    int e0 = rp[node], e1 = rp[node + 1];
    for (int e = e0; e < e1; e++) {
        int eid = ex[e];
        int sidx = srcp[eid];
        float a = eap[eid];
        const int4* row = sfeat + (size_t)sidx * s4;
        int4 v0 = row[lane];
        int4 v1 = row[lane + 32];
        const __half2* h0 = (const __half2*)&v0;
        const __half2* h1 = (const __half2*)&v1;
#pragma unroll
        for (int q = 0; q < 4; q++) {
            float2 f0 = __half22float2(h0[q]);
            float2 f1 = __half22float2(h1[q]);
            float vals[4] = {f0.x, f0.y, f1.x, f1.y};
            int js[4] = {2 * q, 2 * q + 1, 8 + 2 * q, 8 + 2 * q + 1};
#pragma unroll
            for (int u = 0; u < 4; u++) {
                int j = js[u];
                float msg = fmaxf(vals[u] + a * wv[j], 0.f) + 1e-7f;
                float mn = fmaxf(m[j], msg);
                float scale = __expf(m[j] - mn);
                float pr = __expf(msg - mn);
                s[j] = s[j] * scale + pr;
                tt[j] = tt[j] * scale + msg * pr;
                m[j] = mn;
            }
        }
    }

    const int4* drow = dfeat + (size_t)node * d4;
    int4 d0 = drow[lane];
    int4 d1 = drow[lane + 32];
    const __half2* dh0 = (const __half2*)&d0;
    const __half2* dh1 = (const __half2*)&d1;

    int4 o0, o1;
    __half2* oh0 = (__half2*)&o0;
    __half2* oh1 = (__half2*)&o1;
#pragma unroll
    for (int q = 0; q < 4; q++) {
        float2 dv0 = __half22float2(dh0[q]);
        float2 dv1 = __half22float2(dh1[q]);
        float a0 = tt[2 * q] / (s[2 * q] + 1e-16f) + dv0.x;
        float a1 = tt[2 * q + 1] / (s[2 * q + 1] + 1e-16f) + dv0.y;
        float b0 = tt[8 + 2 * q] / (s[8 + 2 * q] + 1e-16f) + dv1.x;
        float b1 = tt[8 + 2 * q + 1] / (s[8 + 2 * q + 1] + 1e-16f) + dv1.y;
        oh0[q] = __floats2half2_rn(a0, a1);
        oh1[q] = __floats2half2_rn(b0, b1);
    }
    int4* orow = (int4*)(oh + ((size_t)p * NN + node) * HC);
    orow[lane] = o0;
    orow[lane + 32] = o1;
}

// ---------------- fp16 GEMM: 128x128x64, cp.async 3-stage, ldmatrix --------------
#define BM 128
#define BN 128
#define BK 64
#define BKH 72
#define STG 3
#define TILE_BYTES (BM * BKH * 2)
#define STAGE_B (2 * TILE_BYTES)
#define DSMEM (STG * STAGE_B)

__device__ __forceinline__ void mma_f16(float* c, const uint32_t* a, uint32_t b0, uint32_t b1) {
    asm volatile(
        "mma.sync.aligned.m16n8k16.row.col.f32.f16.f16.f32 "
        "{%0,%1,%2,%3}, {%4,%5,%6,%7}, {%8,%9}, {%0,%1,%2,%3};"
        : "+f"(c[0]), "+f"(c[1]), "+f"(c[2]), "+f"(c[3])
        : "r"(a[0]), "r"(a[1]), "r"(a[2]), "r"(a[3]), "r"(b0), "r"(b1));
}

__device__ __forceinline__ void ldsm4(uint32_t* r, uint32_t addr) {
    asm volatile("ldmatrix.sync.aligned.m8n8.x4.shared.b16 {%0,%1,%2,%3}, [%4];"
                 : "=r"(r[0]), "=r"(r[1]), "=r"(r[2]), "=r"(r[3]) : "r"(addr));
}

__device__ __forceinline__ void cp16(uint32_t saddr, const void* gaddr, int srcbytes) {
    asm volatile("cp.async.cg.shared.global [%0], [%1], 16, %2;"
                 :: "r"(saddr), "l"(gaddr), "r"(srcbytes));
}

__global__ __launch_bounds__(256, 2) void k_hgemm(
    const __half* __restrict__ A0, const __half* __restrict__ A1, int nsplit,
    const __half* __restrict__ B,
    int M, int K, int Ncols, int mode,
    const float* __restrict__ gv, const float* __restrict__ bv,
    const float* __restrict__ mv, const float* __restrict__ vv,
    float* __restrict__ Cf, __half* __restrict__ Ch)
{
    extern __shared__ __align__(128) char smc[];
    uint32_t sbase = (uint32_t)__cvta_generic_to_shared(smc);

    int tid = threadIdx.x;
    int tileM = blockIdx.y * BM, tileN = blockIdx.x * BN;
    const __half* A = (tileN >= nsplit) ? A1 : A0;
    int warp = tid >> 5, lane = tid & 31;
    int g8 = lane >> 2, t4 = lane & 3;
    int wm = (warp & 1) * 64;
    int wn = (warp >> 1) * 32;

    const __half* Ag = A + (size_t)tileM * K;
    const __half* Bg = B + (size_t)tileN * K;

    int rA[4], cA[4], szA[4];
    uint32_t dA[4], dB[4];
#pragma unroll
    for (int i = 0; i < 4; i++) {
        int q = tid + i * 256;
        rA[i] = q >> 3;
        cA[i] = (q & 7) * 8;
        szA[i] = (tileM + rA[i]) < M ? 16 : 0;
        dA[i] = sbase + (uint32_t)((rA[i] * BKH + cA[i]) * 2);
        dB[i] = dA[i] + TILE_BYTES;
    }

    int mrowA = (lane & 7) + ((lane >> 3) & 1) * 8;
    int kcolA = (lane >> 4) * 8;
    uint32_t aOff = (uint32_t)(((wm + mrowA) * BKH + kcolA) * 2);
    int nrowB = ((lane >> 4) & 1) * 8 + (lane & 7);
    int kcolB = ((lane >> 3) & 1) * 8;
    uint32_t bOff = (uint32_t)(TILE_BYTES + ((wn + nrowB) * BKH + kcolB) * 2);

    float acc[4][4][4];
#pragma unroll
    for (int i = 0; i < 4; i++)
#pragma unroll
        for (int j = 0; j < 4; j++)
#pragma unroll
            for (int r = 0; r < 4; r++) acc[i][j][r] = 0.f;

    int nt = K / BK;

#define HISSUE(tile, stage)                                                     \
    do {                                                                        \
        int kb_ = (tile) * BK;                                                  \
        uint32_t so_ = (uint32_t)((stage) * STAGE_B);                           \
        _Pragma("unroll")                                                       \
        for (int ii = 0; ii < 4; ii++) {                                        \
            cp16(dA[ii] + so_, Ag + (size_t)rA[ii] * K + kb_ + cA[ii], szA[ii]);\
            cp16(dB[ii] + so_, Bg + (size_t)rA[ii] * K + kb_ + cA[ii], 16);     \
        }                                                                       \
    } while (0)

#pragma unroll
    for (int s = 0; s < STG - 1; s++) {
        if (s < nt) HISSUE(s, s);
        asm volatile("cp.async.commit_group;");
    }

    int stage = 0;
    for (int t = 0; t < nt; t++) {
        asm volatile("cp.async.wait_group %0;" :: "n"(STG - 2));
        __syncthreads();

        int ntile = t + STG - 1;
        int nstage = stage + STG - 1;
        if (nstage >= STG) nstage -= STG;
        if (ntile < nt) HISSUE(ntile, nstage);
        asm volatile("cp.async.commit_group;");

        uint32_t stg = sbase + (uint32_t)(stage * STAGE_B);

#pragma unroll
        for (int kk = 0; kk < 4; kk++) {
            uint32_t kby = (uint32_t)(kk * 16 * 2);
            uint32_t af[4][4], bfr[2][4];
#pragma unroll
            for (int i = 0; i < 4; i++)
                ldsm4(af[i], stg + aOff + (uint32_t)(i * 16 * BKH * 2) + kby);
#pragma unroll
            for (int jp = 0; jp < 2; jp++)
                ldsm4(bfr[jp], stg + bOff + (uint32_t)(jp * 16 * BKH * 2) + kby);
#pragma unroll
            for (int j = 0; j < 4; j++) {
                uint32_t b0 = bfr[j >> 1][(j & 1) * 2];
                uint32_t b1 = bfr[j >> 1][(j & 1) * 2 + 1];
#pragma unroll
                for (int i = 0; i < 4; i++) mma_f16(acc[i][j], af[i], b0, b1);
            }
        }
        if (++stage == STG) stage = 0;
    }

    float cs[4][2], cb[4][2], cm[4][2];
    if (mode == 1) {
#pragma unroll
        for (int j = 0; j < 4; j++) {
            int c = tileN + wn + j * 8 + t4 * 2;
#pragma unroll
            for (int q = 0; q < 2; q++) {
                cs[j][q] = gv[c + q] * rsqrtf(vv[c + q] + 1e-5f);
                cb[j][q] = bv[c + q];
                cm[j][q] = mv[c + q];
            }
        }
    }

#pragma unroll
    for (int i = 0; i < 4; i++) {
#pragma unroll
        for (int h8 = 0; h8 < 2; h8++) {
            int r = tileM + wm + i * 16 + g8 + h8 * 8;
            if (r >= M) continue;
#pragma unroll
            for (int j = 0; j < 4; j++) {
                int c = tileN + wn + j * 8 + t4 * 2;
                float v0 = acc[i][j][h8 * 2 + 0];
                float v1 = acc[i][j][h8 * 2 + 1];
                if (mode == 1) {
                    v0 = fmaxf((v0 - cm[j][0]) * cs[j][0] + cb[j][0], 0.f);
                    v1 = fmaxf((v1 - cm[j][1]) * cs[j][1] + cb[j][1], 0.f);
                    __half2 hv;
                    hv.x = __float2half(v0);
                    hv.y = __float2half(v1);
                    *(__half2*)(Ch + (size_t)r * Ncols + c) = hv;
                } else if (mode == 2) {
                    v0 = v0 > 0.f ? v0 : 0.01f * v0;
                    v1 = v1 > 0.f ? v1 : 0.01f * v1;
                    __half2 hv;
                    hv.x = __float2half(v0);
                    hv.y = __float2half(v1);
                    *(__half2*)(Ch + (size_t)r * Ncols + c) = hv;
                } else if (mode == 3) {
                    __half2 hv;
                    hv.x = __float2half(v0);
                    hv.y = __float2half(v1);
                    *(__half2*)(Ch + (size_t)r * Ncols + c) = hv;
                } else {
                    *(float2*)(Cf + (size_t)r * Ncols + c) = make_float2(v0, v1);
                }
            }
        }
    }
}

// ---------------- host orchestration (single stream) ----------------
extern "C" void kernel_launch(void* const* d_in, const int* in_sizes, int n_in,
                              void* d_out, int out_size) {
    const float* x  = (const float*)d_in[0];
    const int*   ei = (const int*)d_in[1];
    const float* ea = (const float*)d_in[2];
    int base = 3;
    if (n_in > 19) base = 3 + (n_in - 19);
    const float* l0_src  = (const float*)d_in[base + 0];
    const float* l0_dst  = (const float*)d_in[base + 1];
    const float* l0_edge = (const float*)d_in[base + 2];
    const float* l0_w1   = (const float*)d_in[base + 3];
    const float* l0_g    = (const float*)d_in[base + 4];
    const float* l0_b    = (const float*)d_in[base + 5];
    const float* l0_m    = (const float*)d_in[base + 6];
    const float* l0_v    = (const float*)d_in[base + 7];
    const float* l0_w2   = (const float*)d_in[base + 8];
    const float* l1_edge = (const float*)d_in[base + 9];
    const float* l1_w1   = (const float*)d_in[base + 10];
    const float* l1_g    = (const float*)d_in[base + 11];
    const float* l1_b    = (const float*)d_in[base + 12];
    const float* l1_m    = (const float*)d_in[base + 13];
    const float* l1_v    = (const float*)d_in[base + 14];
    const float* l1_w2   = (const float*)d_in[base + 15];
    float* out = (float*)d_out;

    __half *sfdf, *x1h, *xh, *ob, *hb, *wcat, *w01, *w02c, *w11, *w12c;
    int *rowptr, *cursor, *eidx;
    cudaGetSymbolAddress((void**)&sfdf, g_sfdf);
    cudaGetSymbolAddress((void**)&x1h, g_x1);
    cudaGetSymbolAddress((void**)&xh, g_xh);
    cudaGetSymbolAddress((void**)&ob, g_ob);
    cudaGetSymbolAddress((void**)&hb, g_hb);
    cudaGetSymbolAddress((void**)&wcat, g_wcat);
    cudaGetSymbolAddress((void**)&w01, g_w01);
    cudaGetSymbolAddress((void**)&w02c, g_w02c);
    cudaGetSymbolAddress((void**)&w11, g_w11);
    cudaGetSymbolAddress((void**)&w12c, g_w12c);
    cudaGetSymbolAddress((void**)&rowptr, g_rowptr);
    cudaGetSymbolAddress((void**)&cursor, g_cursor);
    cudaGetSymbolAddress((void**)&eidx, g_eidx);

    cudaFuncSetAttribute(k_hgemm, cudaFuncAttributeMaxDynamicSharedMemorySize, DSMEM);

    const int* dstBoth = ei + ETOT;
    const int BIG = 1 << 30;

    // ---- fp16 operand conversion (4 launches) ----
    k_half<<<(NN * FINC + 255) / 256, 256>>>(x, xh, NN * FINC);
    k_half_cat2<<<(4 * HC * FINC + 255) / 256, 256>>>(l0_src, l0_dst, wcat);
    k_half2x<<<(4 * H2C * HC + 255) / 256, 256>>>(l0_w1, w01, l1_w1, w11, 2 * H2C * HC);
    k_half_w2cat2<<<(4 * HC * H2C + 255) / 256, 256>>>(l0_w2, w02c, l1_w2, w12c);

    // ---- CSR build ----
    k_zero_int<<<(2 * NN + 255) / 256, 256>>>(cursor, 2 * NN);
    k_count_deg2<<<(2 * LPART + 255) / 256, 256>>>(dstBoth, cursor);
    k_scan2<<<2, 1024>>>(cursor, rowptr);
    k_copy_rp2<<<(2 * NN + 255) / 256, 256>>>(rowptr, cursor);
    k_scatter2<<<(2 * LPART + 255) / 256, 256>>>(dstBoth, cursor, eidx);
    k_sort_buckets2<<<(2 * NN + 127) / 128, 128>>>(rowptr, eidx);

    dim3 blk(256);
    int gy = (NN + BM - 1) / BM;
    dim3 gproj(2048 / BN, gy), g512(HC / BN, gy), g2048(2048 / BN, gy);

    // ---- layer 0 ----
    k_hgemm<<<gproj, blk, DSMEM>>>(xh, xh, BIG, wcat, NN, FINC, 2048, 3,
                                   nullptr, nullptr, nullptr, nullptr, nullptr, sfdf);
    k_agg2<<<(2 * NN) / 4, 128>>>(sfdf, 1024, 2048, sfdf + 512, 1024, 2048,
                                  l0_edge, ea, ei, rowptr, eidx, ob);
    k_hgemm<<<g2048, blk, DSMEM>>>(ob, ob + (size_t)NN * HC, 1024, w01,
                                   NN, HC, 2048, 1, l0_g, l0_b, l0_m, l0_v,
                                   nullptr, hb);
    k_hgemm<<<g512, blk, DSMEM>>>(hb, hb, BIG, w02c, NN, 2048, HC, 2,
                                  nullptr, nullptr, nullptr, nullptr, nullptr, x1h);

    // ---- layer 1 ----
    k_agg2<<<(2 * NN) / 4, 128>>>(x1h, 0, HC, x1h, 0, HC,
                                  l1_edge, ea, ei, rowptr, eidx, ob);
    k_hgemm<<<g2048, blk, DSMEM>>>(ob, ob + (size_t)NN * HC, 1024, w11,
                                   NN, HC, 2048, 1, l1_g, l1_b, l1_m, l1_v,
                                   nullptr, hb);
    k_hgemm<<<g512, blk, DSMEM>>>(hb, hb, BIG, w12c, NN, 2048, HC, 0,
                                  nullptr, nullptr, nullptr, nullptr, out, nullptr);
}